// round 2
// baseline (speedup 1.0000x reference)
#include <cuda_runtime.h>
#include <math.h>

#define HDIM 64
#define VOCAB 50000
#define NTD 8192
#define NBU 8191
#define LBU 4096
#define WSTR 68   // padded stride for weight matrices in shared (float4-aligned, bank-friendly)

// ---------------- device scratch (static allocations only) ----------------
__device__ float g_ET_td[(size_t)VOCAB * HDIM];   // E_td transposed: (V, H)
__device__ float g_ET_bu[(size_t)VOCAB * HDIM];
__device__ float g_zx_td[NTD * HDIM];
__device__ float g_rx_td[NTD * HDIM];
__device__ float g_hx_td[NTD * HDIM];
__device__ float g_zx_bu[NBU * HDIM];
__device__ float g_rx_bu[NBU * HDIM];
__device__ float g_hx_bu[NBU * HDIM];
__device__ float g_h_td[(NTD + 1) * HDIM];
__device__ float g_h_bu[NBU * HDIM];
__device__ float g_tdmax[64 * HDIM];

__device__ __forceinline__ float sigmf(float x) { return 1.0f / (1.0f + expf(-x)); }

// ---------------- kernel 1: transpose E (H,V) -> ET (V,H), zero td root ----------------
__global__ void k_transpose(const float* __restrict__ E_td, const float* __restrict__ E_bu) {
    __shared__ float tile[64][33];
    const float* E = (blockIdx.y == 0) ? E_td : E_bu;
    float* ET = (blockIdx.y == 0) ? g_ET_td : g_ET_bu;
    int v0 = blockIdx.x * 32;
#pragma unroll
    for (int it = 0; it < 8; it++) {
        int e = it * 256 + threadIdx.x;
        int h = e >> 5, vi = e & 31;
        int v = v0 + vi;
        tile[h][vi] = (v < VOCAB) ? E[(size_t)h * VOCAB + v] : 0.f;
    }
    __syncthreads();
#pragma unroll
    for (int it = 0; it < 8; it++) {
        int e = it * 256 + threadIdx.x;
        int vi = e >> 6, h = e & 63;
        int v = v0 + vi;
        if (v < VOCAB) ET[v * 64 + h] = tile[h][vi];
    }
    if (blockIdx.x == 0 && blockIdx.y == 0 && threadIdx.x < 64)
        g_h_td[threadIdx.x] = 0.f;   // node_h[0] = 0
}

// ---------------- kernel 2: fused embedding gather + gate pre-activations ----------------
// zx = xe @ Wz^T + bz, rx = ..., hx = ...; bu leaves also get h = (1-sigm(zx))*tanh(hx)
__global__ void __launch_bounds__(256) k_embed(
    const float* __restrict__ word_td, const int* __restrict__ idx_td,
    const float* __restrict__ word_bu, const int* __restrict__ idx_bu,
    const float* __restrict__ Wz_td, const float* __restrict__ Wr_td, const float* __restrict__ Wh_td,
    const float* __restrict__ bz_td, const float* __restrict__ br_td, const float* __restrict__ bh_td,
    const float* __restrict__ Wz_bu, const float* __restrict__ Wr_bu, const float* __restrict__ Wh_bu,
    const float* __restrict__ bz_bu, const float* __restrict__ br_bu, const float* __restrict__ bh_bu,
    int nblk)
{
    extern __shared__ float sm[];
    float* sW = sm;                       // 3 * 64 * WSTR  (transposed: sW[g][k*WSTR + h])
    float* sb = sW + 3 * 64 * WSTR;       // 3 * 64
    float* sWord = sb + 192;              // 16 * 64
    float* sXe = sWord + 1024;            // 16 * 64
    int* sIdx = (int*)(sXe + 1024);       // 16 * 64

    bool is_td = (blockIdx.x < nblk);
    const float* word = is_td ? word_td : word_bu;
    const int* idx = is_td ? idx_td : idx_bu;
    const float* ET = is_td ? g_ET_td : g_ET_bu;
    const float* Wz = is_td ? Wz_td : Wz_bu;
    const float* Wr = is_td ? Wr_td : Wr_bu;
    const float* Wh = is_td ? Wh_td : Wh_bu;
    const float* bz = is_td ? bz_td : bz_bu;
    const float* br = is_td ? br_td : br_bu;
    const float* bh = is_td ? bh_td : bh_bu;
    float* zx = is_td ? g_zx_td : g_zx_bu;
    float* rx = is_td ? g_rx_td : g_rx_bu;
    float* hx = is_td ? g_hx_td : g_hx_bu;
    int nNodes = is_td ? NTD : NBU;

    // load W (transposed) into shared
    for (int g = 0; g < 3; g++) {
        const float* Wg = (g == 0) ? Wz : (g == 1) ? Wr : Wh;
        for (int e = threadIdx.x; e < 4096; e += 256) {
            int hh = e >> 6, kk = e & 63;
            sW[g * 64 * WSTR + kk * WSTR + hh] = Wg[e];
        }
    }
    if (threadIdx.x < 64) sb[threadIdx.x] = bz[threadIdx.x];
    else if (threadIdx.x < 128) sb[threadIdx.x] = br[threadIdx.x - 64];
    else if (threadIdx.x < 192) sb[threadIdx.x] = bh[threadIdx.x - 128];
    __syncthreads();

    int slot = threadIdx.x >> 4;    // 0..15 (node lane within block)
    int t = threadIdx.x & 15;
    int h4 = t * 4;
    int blkBr = is_td ? blockIdx.x : blockIdx.x - nblk;

    for (int base = blkBr * 16; base < nNodes; base += nblk * 16) {
        int n = base + slot;
        bool act = (n < nNodes);
        if (act) {
            *(int4*)&sIdx[slot * 64 + h4] = *(const int4*)&idx[n * 64 + h4];
            *(float4*)&sWord[slot * 64 + h4] = *(const float4*)&word[n * 64 + h4];
        }
        __syncthreads();
        float4 acc = make_float4(0.f, 0.f, 0.f, 0.f);
        if (act) {
            const int* ip = &sIdx[slot * 64];
            const float* wp = &sWord[slot * 64];
#pragma unroll 8
            for (int w = 0; w < 64; w++) {
                float4 e4 = *(const float4*)&ET[ip[w] * 64 + h4];
                float wv = wp[w];
                acc.x += e4.x * wv; acc.y += e4.y * wv;
                acc.z += e4.z * wv; acc.w += e4.w * wv;
            }
        }
        *(float4*)&sXe[slot * 64 + h4] = acc;
        __syncthreads();
        if (act) {
            const float* xe = &sXe[slot * 64];
            float4 az = *(const float4*)&sb[0 * 64 + h4];
            float4 ar = *(const float4*)&sb[1 * 64 + h4];
            float4 ah = *(const float4*)&sb[2 * 64 + h4];
#pragma unroll 4
            for (int k = 0; k < 64; k++) {
                float x = xe[k];
                float4 wz4 = *(const float4*)&sW[0 * 64 * WSTR + k * WSTR + h4];
                float4 wr4 = *(const float4*)&sW[1 * 64 * WSTR + k * WSTR + h4];
                float4 wh4 = *(const float4*)&sW[2 * 64 * WSTR + k * WSTR + h4];
                az.x += wz4.x * x; az.y += wz4.y * x; az.z += wz4.z * x; az.w += wz4.w * x;
                ar.x += wr4.x * x; ar.y += wr4.y * x; ar.z += wr4.z * x; ar.w += wr4.w * x;
                ah.x += wh4.x * x; ah.y += wh4.y * x; ah.z += wh4.z * x; ah.w += wh4.w * x;
            }
            if (is_td || n >= LBU) {
                *(float4*)&zx[n * 64 + h4] = az;
                *(float4*)&rx[n * 64 + h4] = ar;
                *(float4*)&hx[n * 64 + h4] = ah;
            } else {
                // bottom-up leaf: h = (1 - sigmoid(zx)) * tanh(hx)
                float4 lh;
                lh.x = (1.f - sigmf(az.x)) * tanhf(ah.x);
                lh.y = (1.f - sigmf(az.y)) * tanhf(ah.y);
                lh.z = (1.f - sigmf(az.z)) * tanhf(ah.z);
                lh.w = (1.f - sigmf(az.w)) * tanhf(ah.w);
                *(float4*)&g_h_bu[n * 64 + h4] = lh;
            }
        }
        __syncthreads();
    }
}

// ---------------- kernel 3: one tree level (td level s fused with bu level s) ----------------
__global__ void __launch_bounds__(256) k_step(
    int td_lo, int td_cnt, int bu_lo, int bu_cnt, int td_blocks, int bu_blocks,
    const float* __restrict__ Uz_td, const float* __restrict__ Ur_td, const float* __restrict__ Uh_td,
    const float* __restrict__ Uz_bu, const float* __restrict__ Ur_bu, const float* __restrict__ Uh_bu)
{
    extern __shared__ float sm[];
    float* sU = sm;                      // 3 * 64 * WSTR
    float* sHp = sU + 3 * 64 * WSTR;     // 16 * 64
    float* sHr = sHp + 1024;             // 16 * 64

    bool is_td = (blockIdx.x < td_blocks);
    const float* Uz = is_td ? Uz_td : Uz_bu;
    const float* Ur = is_td ? Ur_td : Ur_bu;
    const float* Uh = is_td ? Uh_td : Uh_bu;

    for (int g = 0; g < 3; g++) {
        const float* Ug = (g == 0) ? Uz : (g == 1) ? Ur : Uh;
        for (int e = threadIdx.x; e < 4096; e += 256) {
            int hh = e >> 6, kk = e & 63;
            sU[g * 64 * WSTR + kk * WSTR + hh] = Ug[e];
        }
    }
    __syncthreads();

    int slot = threadIdx.x >> 4;
    int t = threadIdx.x & 15;
    int h4 = t * 4;
    int blkBr = is_td ? blockIdx.x : blockIdx.x - td_blocks;
    int nBlk = is_td ? td_blocks : bu_blocks;
    int cnt = is_td ? td_cnt : bu_cnt;
    int lo = is_td ? td_lo : bu_lo;

    for (int base = blkBr * 16; base < cnt; base += nBlk * 16) {
        int r = base + slot;
        bool act = (r < cnt);
        float4 hp = make_float4(0.f, 0.f, 0.f, 0.f);
        float4 az, ar, ah;
        int outRow = 0;
        if (act) {
            if (is_td) {
                int o = lo + r;
                int p = (o - 1) >> 1;
                hp = *(const float4*)&g_h_td[p * 64 + h4];
                int gi = o - 1;
                az = *(const float4*)&g_zx_td[gi * 64 + h4];
                ar = *(const float4*)&g_rx_td[gi * 64 + h4];
                ah = *(const float4*)&g_hx_td[gi * 64 + h4];
                outRow = o;
            } else {
                int j = lo + r;
                float4 a = *(const float4*)&g_h_bu[(2 * j) * 64 + h4];
                float4 b = *(const float4*)&g_h_bu[(2 * j + 1) * 64 + h4];
                hp = make_float4(a.x + b.x, a.y + b.y, a.z + b.z, a.w + b.w);
                int gi = LBU + j;
                az = *(const float4*)&g_zx_bu[gi * 64 + h4];
                ar = *(const float4*)&g_rx_bu[gi * 64 + h4];
                ah = *(const float4*)&g_hx_bu[gi * 64 + h4];
                outRow = gi;
            }
        }
        *(float4*)&sHp[slot * 64 + h4] = hp;
        __syncthreads();
        float4 z = make_float4(0, 0, 0, 0), rr = make_float4(0, 0, 0, 0);
        if (act) {
            float4 mz = az, mr = ar;
            const float* hpv = &sHp[slot * 64];
#pragma unroll 4
            for (int k = 0; k < 64; k++) {
                float x = hpv[k];
                float4 uz4 = *(const float4*)&sU[0 * 64 * WSTR + k * WSTR + h4];
                float4 ur4 = *(const float4*)&sU[1 * 64 * WSTR + k * WSTR + h4];
                mz.x += uz4.x * x; mz.y += uz4.y * x; mz.z += uz4.z * x; mz.w += uz4.w * x;
                mr.x += ur4.x * x; mr.y += ur4.y * x; mr.z += ur4.z * x; mr.w += ur4.w * x;
            }
            z = make_float4(sigmf(mz.x), sigmf(mz.y), sigmf(mz.z), sigmf(mz.w));
            rr = make_float4(sigmf(mr.x), sigmf(mr.y), sigmf(mr.z), sigmf(mr.w));
        }
        float4 hr = make_float4(hp.x * rr.x, hp.y * rr.y, hp.z * rr.z, hp.w * rr.w);
        *(float4*)&sHr[slot * 64 + h4] = act ? hr : make_float4(0, 0, 0, 0);
        __syncthreads();
        if (act) {
            float4 mh = ah;
            const float* hrv = &sHr[slot * 64];
#pragma unroll 4
            for (int k = 0; k < 64; k++) {
                float x = hrv[k];
                float4 uh4 = *(const float4*)&sU[2 * 64 * WSTR + k * WSTR + h4];
                mh.x += uh4.x * x; mh.y += uh4.y * x; mh.z += uh4.z * x; mh.w += uh4.w * x;
            }
            float4 c = make_float4(tanhf(mh.x), tanhf(mh.y), tanhf(mh.z), tanhf(mh.w));
            float4 hn;
            hn.x = z.x * hp.x + (1.f - z.x) * c.x;
            hn.y = z.y * hp.y + (1.f - z.y) * c.y;
            hn.z = z.z * hp.z + (1.f - z.z) * c.z;
            hn.w = z.w * hp.w + (1.f - z.w) * c.w;
            if (is_td) *(float4*)&g_h_td[outRow * 64 + h4] = hn;
            else       *(float4*)&g_h_bu[outRow * 64 + h4] = hn;
        }
        __syncthreads();
    }
}

// ---------------- kernel 4: partial max over td leaf rows 4096..8192 ----------------
__global__ void k_tdmax() {
    int h = threadIdx.x;       // 64 threads
    int b = blockIdx.x;        // 64 blocks
    float m = -1e30f;
    for (int r = 4096 + b; r <= NTD; r += 64)
        m = fmaxf(m, g_h_td[r * 64 + h]);
    g_tdmax[b * 64 + h] = m;
}

// ---------------- kernel 5: head (max-reduce + MLP + softmax) ----------------
__global__ void k_final(const float* __restrict__ W1, const float* __restrict__ b1,
                        const float* __restrict__ W4, const float* __restrict__ b4,
                        float* __restrict__ out) {
    __shared__ float fs[128], f1[64], lg[4];
    int tid = threadIdx.x;  // 128 threads
    if (tid < 64) {
        float m = -1e30f;
        for (int b = 0; b < 64; b++) m = fmaxf(m, g_tdmax[b * 64 + tid]);
        fs[tid] = m;
    } else {
        fs[tid] = g_h_bu[(NBU - 1) * 64 + (tid - 64)];
    }
    __syncthreads();
    if (tid < 64) {
        float a = b1[tid];
#pragma unroll 4
        for (int k = 0; k < 128; k++) a += W1[tid * 128 + k] * fs[k];
        f1[tid] = fmaxf(a, 0.f);
    }
    __syncthreads();
    if (tid < 4) {
        float a = b4[tid];
        for (int k = 0; k < 64; k++) a += W4[tid * 64 + k] * f1[k];
        lg[tid] = a;
    }
    __syncthreads();
    if (tid == 0) {
        float mx = fmaxf(fmaxf(lg[0], lg[1]), fmaxf(lg[2], lg[3]));
        float e0 = expf(lg[0] - mx), e1 = expf(lg[1] - mx);
        float e2 = expf(lg[2] - mx), e3 = expf(lg[3] - mx);
        float s = e0 + e1 + e2 + e3;
        out[0] = e0 / s; out[1] = e1 / s; out[2] = e2 / s; out[3] = e3 / s;
    }
}

// ---------------- launch ----------------
extern "C" void kernel_launch(void* const* d_in, const int* in_sizes, int n_in,
                              void* d_out, int out_size) {
    const float* td_x_word = (const float*)d_in[0];
    const float* bu_x_word = (const float*)d_in[1];
    const float* E_td  = (const float*)d_in[2];
    const float* Wz_td = (const float*)d_in[3];
    const float* Uz_td = (const float*)d_in[4];
    const float* bz_td = (const float*)d_in[5];
    const float* Wr_td = (const float*)d_in[6];
    const float* Ur_td = (const float*)d_in[7];
    const float* br_td = (const float*)d_in[8];
    const float* Wh_td = (const float*)d_in[9];
    const float* Uh_td = (const float*)d_in[10];
    const float* bh_td = (const float*)d_in[11];
    const float* E_bu  = (const float*)d_in[12];
    const float* Wz_bu = (const float*)d_in[13];
    const float* Uz_bu = (const float*)d_in[14];
    const float* bz_bu = (const float*)d_in[15];
    const float* Wr_bu = (const float*)d_in[16];
    const float* Ur_bu = (const float*)d_in[17];
    const float* br_bu = (const float*)d_in[18];
    const float* Wh_bu = (const float*)d_in[19];
    const float* Uh_bu = (const float*)d_in[20];
    const float* bh_bu = (const float*)d_in[21];
    const float* W1 = (const float*)d_in[22];
    const float* b1 = (const float*)d_in[23];
    const float* W4 = (const float*)d_in[24];
    const float* b4 = (const float*)d_in[25];

    // resolve index tensors by unique element counts (robust to metadata ordering
    // of the trailing five inputs)
    const int* idx_td = (const int*)d_in[26];
    const int* idx_bu = (const int*)d_in[27];
    for (int i = 26; i < n_in; i++) {
        if (in_sizes[i] == NTD * 64) idx_td = (const int*)d_in[i];
        else if (in_sizes[i] == NBU * 64) idx_bu = (const int*)d_in[i];
    }

    const int smemE = (3 * 64 * WSTR + 192 + 1024 + 1024 + 1024) * 4;
    const int smemS = (3 * 64 * WSTR + 1024 + 1024) * 4;
    cudaFuncSetAttribute(k_embed, cudaFuncAttributeMaxDynamicSharedMemorySize, smemE);
    cudaFuncSetAttribute(k_step, cudaFuncAttributeMaxDynamicSharedMemorySize, smemS);

    k_transpose<<<dim3((VOCAB + 31) / 32, 2), 256>>>(E_td, E_bu);

    const int NBLK = 148;
    k_embed<<<2 * NBLK, 256, smemE>>>(td_x_word, idx_td, bu_x_word, idx_bu,
                                      Wz_td, Wr_td, Wh_td, bz_td, br_td, bh_td,
                                      Wz_bu, Wr_bu, Wh_bu, bz_bu, br_bu, bh_bu, NBLK);

    for (int s = 1; s <= 13; s++) {
        int td_lo = (1 << s) - 1;
        int td_cnt = (s < 13) ? (1 << s) : 2;
        int bu_cnt = (s <= 12) ? (1 << (12 - s)) : 0;
        int bu_lo = (s <= 12) ? (4096 - (1 << (13 - s))) : 0;
        int tb = (td_cnt + 15) / 16; if (tb > 128) tb = 128;
        int bb = bu_cnt ? ((bu_cnt + 15) / 16) : 0; if (bb > 128) bb = 128;
        k_step<<<tb + bb, 256, smemS>>>(td_lo, td_cnt, bu_lo, bu_cnt, tb, bb,
                                        Uz_td, Ur_td, Uh_td, Uz_bu, Ur_bu, Uh_bu);
    }

    k_tdmax<<<64, 64>>>();
    k_final<<<1, 128>>>(W1, b1, W4, b4, (float*)d_out);
}

// round 5
// speedup vs baseline: 1.0892x; 1.0892x over previous
#include <cuda_runtime.h>
#include <math.h>

#define HDIM 64
#define VOCAB 50000
#define NTD 8192
#define NBU 8191
#define LBU 4096
#define WSTR 68     // padded stride for weight matrices in shared
#define PBLK 128    // persistent tree-kernel blocks (1 per SM, all resident)

// ---------------- device scratch (static allocations only) ----------------
__device__ float g_ET_td[(size_t)VOCAB * HDIM];   // E_td transposed: (V, H)
__device__ float g_ET_bu[(size_t)VOCAB * HDIM];
__device__ float g_zx_td[NTD * HDIM];
__device__ float g_rx_td[NTD * HDIM];
__device__ float g_hx_td[NTD * HDIM];
__device__ float g_zx_bu[NBU * HDIM];
__device__ float g_rx_bu[NBU * HDIM];
__device__ float g_hx_bu[NBU * HDIM];
__device__ float g_h_td[(NTD + 1) * HDIM];
__device__ float g_h_bu[NBU * HDIM];
__device__ float g_tdmax[64 * HDIM];
__device__ int   g_bar[16];           // per-level barrier counters (zeroed by k_transpose)

// ---------------- fast activations (ex2/rcp approx; abs err ~1e-6) ----------------
__device__ __forceinline__ float fex2(float x) { float r; asm("ex2.approx.f32 %0,%1;" : "=f"(r) : "f"(x)); return r; }
__device__ __forceinline__ float frcp(float x) { float r; asm("rcp.approx.f32 %0,%1;" : "=f"(r) : "f"(x)); return r; }
__device__ __forceinline__ float sigmf(float x) { return frcp(1.0f + fex2(-1.4426950408889634f * x)); }
__device__ __forceinline__ float tanhf_fast(float x) { return 2.0f * sigmf(2.0f * x) - 1.0f; }

// ---------------- kernel 1: transpose E (H,V) -> ET (V,H), reset barriers, zero td root ----------------
__global__ void k_transpose(const float* __restrict__ E_td, const float* __restrict__ E_bu) {
    __shared__ float tile[64][33];
    const float* E = (blockIdx.y == 0) ? E_td : E_bu;
    float* ET = (blockIdx.y == 0) ? g_ET_td : g_ET_bu;
    int v0 = blockIdx.x * 32;
#pragma unroll
    for (int it = 0; it < 8; it++) {
        int e = it * 256 + threadIdx.x;
        int h = e >> 5, vi = e & 31;
        int v = v0 + vi;
        tile[h][vi] = (v < VOCAB) ? E[(size_t)h * VOCAB + v] : 0.f;
    }
    __syncthreads();
#pragma unroll
    for (int it = 0; it < 8; it++) {
        int e = it * 256 + threadIdx.x;
        int vi = e >> 6, h = e & 63;
        int v = v0 + vi;
        if (v < VOCAB) ET[v * 64 + h] = tile[h][vi];
    }
    if (blockIdx.x == 0 && blockIdx.y == 0) {
        if (threadIdx.x < 64) g_h_td[threadIdx.x] = 0.f;   // node_h[0] = 0
        if (threadIdx.x >= 64 && threadIdx.x < 80) g_bar[threadIdx.x - 64] = 0;  // reset barriers
    }
}

// ---------------- kernel 2: fused embedding gather + gate pre-activations ----------------
__global__ void __launch_bounds__(256) k_embed(
    const float* __restrict__ word_td, const int* __restrict__ idx_td,
    const float* __restrict__ word_bu, const int* __restrict__ idx_bu,
    const float* __restrict__ Wz_td, const float* __restrict__ Wr_td, const float* __restrict__ Wh_td,
    const float* __restrict__ bz_td, const float* __restrict__ br_td, const float* __restrict__ bh_td,
    const float* __restrict__ Wz_bu, const float* __restrict__ Wr_bu, const float* __restrict__ Wh_bu,
    const float* __restrict__ bz_bu, const float* __restrict__ br_bu, const float* __restrict__ bh_bu,
    int nblk)
{
    extern __shared__ float sm[];
    float* sW = sm;                       // 3 * 64 * WSTR  (transposed: sW[g][k*WSTR + h])
    float* sb = sW + 3 * 64 * WSTR;       // 3 * 64
    float* sWord = sb + 192;              // 16 * 64
    float* sXe = sWord + 1024;            // 16 * 64
    int* sIdx = (int*)(sXe + 1024);       // 16 * 64

    bool is_td = (blockIdx.x < nblk);
    const float* word = is_td ? word_td : word_bu;
    const int* idx = is_td ? idx_td : idx_bu;
    const float* ET = is_td ? g_ET_td : g_ET_bu;
    const float* Wz = is_td ? Wz_td : Wz_bu;
    const float* Wr = is_td ? Wr_td : Wr_bu;
    const float* Wh = is_td ? Wh_td : Wh_bu;
    const float* bz = is_td ? bz_td : bz_bu;
    const float* br = is_td ? br_td : br_bu;
    const float* bh = is_td ? bh_td : bh_bu;
    float* zx = is_td ? g_zx_td : g_zx_bu;
    float* rx = is_td ? g_rx_td : g_rx_bu;
    float* hx = is_td ? g_hx_td : g_hx_bu;
    int nNodes = is_td ? NTD : NBU;

    for (int g = 0; g < 3; g++) {
        const float* Wg = (g == 0) ? Wz : (g == 1) ? Wr : Wh;
        for (int e = threadIdx.x; e < 4096; e += 256) {
            int hh = e >> 6, kk = e & 63;
            sW[g * 64 * WSTR + kk * WSTR + hh] = Wg[e];
        }
    }
    if (threadIdx.x < 64) sb[threadIdx.x] = bz[threadIdx.x];
    else if (threadIdx.x < 128) sb[threadIdx.x] = br[threadIdx.x - 64];
    else if (threadIdx.x < 192) sb[threadIdx.x] = bh[threadIdx.x - 128];
    __syncthreads();

    int slot = threadIdx.x >> 4;
    int t = threadIdx.x & 15;
    int h4 = t * 4;
    int blkBr = is_td ? blockIdx.x : blockIdx.x - nblk;

    for (int base = blkBr * 16; base < nNodes; base += nblk * 16) {
        int n = base + slot;
        bool act = (n < nNodes);
        if (act) {
            *(int4*)&sIdx[slot * 64 + h4] = *(const int4*)&idx[n * 64 + h4];
            *(float4*)&sWord[slot * 64 + h4] = *(const float4*)&word[n * 64 + h4];
        }
        __syncthreads();
        float4 acc = make_float4(0.f, 0.f, 0.f, 0.f);
        if (act) {
            const int* ip = &sIdx[slot * 64];
            const float* wp = &sWord[slot * 64];
#pragma unroll 8
            for (int w = 0; w < 64; w++) {
                float4 e4 = *(const float4*)&ET[ip[w] * 64 + h4];
                float wv = wp[w];
                acc.x += e4.x * wv; acc.y += e4.y * wv;
                acc.z += e4.z * wv; acc.w += e4.w * wv;
            }
        }
        *(float4*)&sXe[slot * 64 + h4] = acc;
        __syncthreads();
        if (act) {
            const float* xe = &sXe[slot * 64];
            float4 az = *(const float4*)&sb[0 * 64 + h4];
            float4 ar = *(const float4*)&sb[1 * 64 + h4];
            float4 ah = *(const float4*)&sb[2 * 64 + h4];
#pragma unroll 4
            for (int k = 0; k < 64; k++) {
                float x = xe[k];
                float4 wz4 = *(const float4*)&sW[0 * 64 * WSTR + k * WSTR + h4];
                float4 wr4 = *(const float4*)&sW[1 * 64 * WSTR + k * WSTR + h4];
                float4 wh4 = *(const float4*)&sW[2 * 64 * WSTR + k * WSTR + h4];
                az.x += wz4.x * x; az.y += wz4.y * x; az.z += wz4.z * x; az.w += wz4.w * x;
                ar.x += wr4.x * x; ar.y += wr4.y * x; ar.z += wr4.z * x; ar.w += wr4.w * x;
                ah.x += wh4.x * x; ah.y += wh4.y * x; ah.z += wh4.z * x; ah.w += wh4.w * x;
            }
            if (is_td || n >= LBU) {
                *(float4*)&zx[n * 64 + h4] = az;
                *(float4*)&rx[n * 64 + h4] = ar;
                *(float4*)&hx[n * 64 + h4] = ah;
            } else {
                float4 lh;
                lh.x = (1.f - sigmf(az.x)) * tanhf_fast(ah.x);
                lh.y = (1.f - sigmf(az.y)) * tanhf_fast(ah.y);
                lh.z = (1.f - sigmf(az.z)) * tanhf_fast(ah.z);
                lh.w = (1.f - sigmf(az.w)) * tanhf_fast(ah.w);
                *(float4*)&g_h_bu[n * 64 + h4] = lh;
            }
        }
        __syncthreads();
    }
}

// ---------------- global software barrier (all PBLK blocks resident) ----------------
__device__ __forceinline__ void gbar(int l) {
    __syncthreads();
    if (threadIdx.x == 0) {
        __threadfence();
        atomicAdd(&g_bar[l], 1);
        while (*((volatile int*)&g_bar[l]) < PBLK) { }
        __threadfence();
    }
    __syncthreads();
}

// ---------------- kernel 3: PERSISTENT tree kernel — all 13 levels + max + head ----------------
__global__ void __launch_bounds__(256) k_tree(
    const float* __restrict__ Uz_td, const float* __restrict__ Ur_td, const float* __restrict__ Uh_td,
    const float* __restrict__ Uz_bu, const float* __restrict__ Ur_bu, const float* __restrict__ Uh_bu,
    const float* __restrict__ W1, const float* __restrict__ b1,
    const float* __restrict__ W4, const float* __restrict__ b4,
    float* __restrict__ out)
{
    extern __shared__ float sm[];
    float* sU = sm;                       // 6 * 64 * WSTR  ([td z,r,h | bu z,r,h], transposed)
    float* sHp = sU + 6 * 64 * WSTR;      // 16 * 64
    float* sHr = sHp + 1024;              // 16 * 64

    // load all six U matrices once
    for (int g = 0; g < 6; g++) {
        const float* Ug = (g == 0) ? Uz_td : (g == 1) ? Ur_td : (g == 2) ? Uh_td
                        : (g == 3) ? Uz_bu : (g == 4) ? Ur_bu : Uh_bu;
        for (int e = threadIdx.x; e < 4096; e += 256) {
            int hh = e >> 6, kk = e & 63;
            sU[g * 64 * WSTR + kk * WSTR + hh] = Ug[e];
        }
    }
    __syncthreads();

    int slot = threadIdx.x >> 4;
    int t = threadIdx.x & 15;
    int h4 = t * 4;

    for (int s = 1; s <= 13; s++) {
        int td_lo = (1 << s) - 1;
        int td_cnt = (s < 13) ? (1 << s) : 2;
        int bu_cnt = (s <= 12) ? (1 << (12 - s)) : 0;
        int bu_lo = (s <= 12) ? (4096 - (1 << (13 - s))) : 0;
        int tiles_td = (td_cnt + 15) >> 4;
        int tiles_bu = (bu_cnt + 15) >> 4;
        int tiles = tiles_td + tiles_bu;

        for (int tile = blockIdx.x; tile < tiles; tile += PBLK) {
            bool is_td = (tile < tiles_td);
            int base = (is_td ? tile : tile - tiles_td) * 16;
            int cnt = is_td ? td_cnt : bu_cnt;
            int ub = is_td ? 0 : 3 * 64 * WSTR;

            int r = base + slot;
            bool act = (r < cnt);
            float4 hp = make_float4(0.f, 0.f, 0.f, 0.f);
            float4 az, ar, ah;
            int outRow = 0;
            if (act) {
                if (is_td) {
                    int o = td_lo + r;
                    int p = (o - 1) >> 1;
                    hp = *(const float4*)&g_h_td[p * 64 + h4];
                    int gi = o - 1;
                    az = *(const float4*)&g_zx_td[gi * 64 + h4];
                    ar = *(const float4*)&g_rx_td[gi * 64 + h4];
                    ah = *(const float4*)&g_hx_td[gi * 64 + h4];
                    outRow = o;
                } else {
                    int j = bu_lo + r;
                    float4 a = *(const float4*)&g_h_bu[(2 * j) * 64 + h4];
                    float4 b = *(const float4*)&g_h_bu[(2 * j + 1) * 64 + h4];
                    hp = make_float4(a.x + b.x, a.y + b.y, a.z + b.z, a.w + b.w);
                    int gi = LBU + j;
                    az = *(const float4*)&g_zx_bu[gi * 64 + h4];
                    ar = *(const float4*)&g_rx_bu[gi * 64 + h4];
                    ah = *(const float4*)&g_hx_bu[gi * 64 + h4];
                    outRow = gi;
                }
            }
            *(float4*)&sHp[slot * 64 + h4] = hp;
            __syncthreads();
            float4 z = make_float4(0, 0, 0, 0), rr = make_float4(0, 0, 0, 0);
            if (act) {
                float4 mz = az, mr = ar;
                const float* hpv = &sHp[slot * 64];
#pragma unroll 4
                for (int k = 0; k < 64; k++) {
                    float x = hpv[k];
                    float4 uz4 = *(const float4*)&sU[ub + 0 * 64 * WSTR + k * WSTR + h4];
                    float4 ur4 = *(const float4*)&sU[ub + 1 * 64 * WSTR + k * WSTR + h4];
                    mz.x += uz4.x * x; mz.y += uz4.y * x; mz.z += uz4.z * x; mz.w += uz4.w * x;
                    mr.x += ur4.x * x; mr.y += ur4.y * x; mr.z += ur4.z * x; mr.w += ur4.w * x;
                }
                z = make_float4(sigmf(mz.x), sigmf(mz.y), sigmf(mz.z), sigmf(mz.w));
                rr = make_float4(sigmf(mr.x), sigmf(mr.y), sigmf(mr.z), sigmf(mr.w));
            }
            float4 hr = make_float4(hp.x * rr.x, hp.y * rr.y, hp.z * rr.z, hp.w * rr.w);
            *(float4*)&sHr[slot * 64 + h4] = act ? hr : make_float4(0, 0, 0, 0);
            __syncthreads();
            if (act) {
                float4 mh = ah;
                const float* hrv = &sHr[slot * 64];
#pragma unroll 4
                for (int k = 0; k < 64; k++) {
                    float x = hrv[k];
                    float4 uh4 = *(const float4*)&sU[ub + 2 * 64 * WSTR + k * WSTR + h4];
                    mh.x += uh4.x * x; mh.y += uh4.y * x; mh.z += uh4.z * x; mh.w += uh4.w * x;
                }
                float4 c = make_float4(tanhf_fast(mh.x), tanhf_fast(mh.y), tanhf_fast(mh.z), tanhf_fast(mh.w));
                float4 hn;
                hn.x = z.x * hp.x + (1.f - z.x) * c.x;
                hn.y = z.y * hp.y + (1.f - z.y) * c.y;
                hn.z = z.z * hp.z + (1.f - z.z) * c.z;
                hn.w = z.w * hp.w + (1.f - z.w) * c.w;
                if (is_td) *(float4*)&g_h_td[outRow * 64 + h4] = hn;
                else       *(float4*)&g_h_bu[outRow * 64 + h4] = hn;
            }
            __syncthreads();
        }
        gbar(s - 1);   // barriers 0..12
    }

    // ---- partial max over td leaf rows (blocks 0..63) ----
    if (blockIdx.x < 64 && threadIdx.x < 64) {
        int h = threadIdx.x, b = blockIdx.x;
        float m = -1e30f;
        for (int r = 4096 + b; r <= NTD; r += 64)
            m = fmaxf(m, g_h_td[r * 64 + h]);
        g_tdmax[b * 64 + h] = m;
    }
    gbar(13);

    // ---- head: reduce + MLP + softmax (block 0) ----
    if (blockIdx.x == 0) {
        __shared__ float fs[128], f1[64], lg[4];
        int tid = threadIdx.x;
        if (tid < 64) {
            float m = -1e30f;
            for (int b = 0; b < 64; b++) m = fmaxf(m, g_tdmax[b * 64 + tid]);
            fs[tid] = m;
        } else if (tid < 128) {
            fs[tid] = g_h_bu[(NBU - 1) * 64 + (tid - 64)];
        }
        __syncthreads();
        if (tid < 64) {
            float a = b1[tid];
#pragma unroll 4
            for (int k = 0; k < 128; k++) a += W1[tid * 128 + k] * fs[k];
            f1[tid] = fmaxf(a, 0.f);
        }
        __syncthreads();
        if (tid < 4) {
            float a = b4[tid];
            for (int k = 0; k < 64; k++) a += W4[tid * 64 + k] * f1[k];
            lg[tid] = a;
        }
        __syncthreads();
        if (tid == 0) {
            float mx = fmaxf(fmaxf(lg[0], lg[1]), fmaxf(lg[2], lg[3]));
            float e0 = expf(lg[0] - mx), e1 = expf(lg[1] - mx);
            float e2 = expf(lg[2] - mx), e3 = expf(lg[3] - mx);
            float sI = e0 + e1 + e2 + e3;
            out[0] = e0 / sI; out[1] = e1 / sI; out[2] = e2 / sI; out[3] = e3 / sI;
        }
    }
}

// ---------------- launch ----------------
extern "C" void kernel_launch(void* const* d_in, const int* in_sizes, int n_in,
                              void* d_out, int out_size) {
    const float* td_x_word = (const float*)d_in[0];
    const float* bu_x_word = (const float*)d_in[1];
    const float* E_td  = (const float*)d_in[2];
    const float* Wz_td = (const float*)d_in[3];
    const float* Uz_td = (const float*)d_in[4];
    const float* bz_td = (const float*)d_in[5];
    const float* Wr_td = (const float*)d_in[6];
    const float* Ur_td = (const float*)d_in[7];
    const float* br_td = (const float*)d_in[8];
    const float* Wh_td = (const float*)d_in[9];
    const float* Uh_td = (const float*)d_in[10];
    const float* bh_td = (const float*)d_in[11];
    const float* E_bu  = (const float*)d_in[12];
    const float* Wz_bu = (const float*)d_in[13];
    const float* Uz_bu = (const float*)d_in[14];
    const float* bz_bu = (const float*)d_in[15];
    const float* Wr_bu = (const float*)d_in[16];
    const float* Ur_bu = (const float*)d_in[17];
    const float* br_bu = (const float*)d_in[18];
    const float* Wh_bu = (const float*)d_in[19];
    const float* Uh_bu = (const float*)d_in[20];
    const float* bh_bu = (const float*)d_in[21];
    const float* W1 = (const float*)d_in[22];
    const float* b1 = (const float*)d_in[23];
    const float* W4 = (const float*)d_in[24];
    const float* b4 = (const float*)d_in[25];

    const int* idx_td = (const int*)d_in[26];
    const int* idx_bu = (const int*)d_in[27];
    for (int i = 26; i < n_in; i++) {
        if (in_sizes[i] == NTD * 64) idx_td = (const int*)d_in[i];
        else if (in_sizes[i] == NBU * 64) idx_bu = (const int*)d_in[i];
    }

    const int smemE = (3 * 64 * WSTR + 192 + 1024 + 1024 + 1024) * 4;
    const int smemT = (6 * 64 * WSTR + 1024 + 1024) * 4;
    cudaFuncSetAttribute(k_embed, cudaFuncAttributeMaxDynamicSharedMemorySize, smemE);
    cudaFuncSetAttribute(k_tree, cudaFuncAttributeMaxDynamicSharedMemorySize, smemT);

    k_transpose<<<dim3((VOCAB + 31) / 32, 2), 256>>>(E_td, E_bu);

    const int NBLK = 148;
    k_embed<<<2 * NBLK, 256, smemE>>>(td_x_word, idx_td, bu_x_word, idx_bu,
                                      Wz_td, Wr_td, Wh_td, bz_td, br_td, bh_td,
                                      Wz_bu, Wr_bu, Wh_bu, bz_bu, br_bu, bh_bu, NBLK);

    k_tree<<<PBLK, 256, smemT>>>(Uz_td, Ur_td, Uh_td, Uz_bu, Ur_bu, Uh_bu,
                                 W1, b1, W4, b4, (float*)d_out);
}

// round 6
// speedup vs baseline: 1.2856x; 1.1802x over previous
#include <cuda_runtime.h>
#include <math.h>

#define HDIM 64
#define VOCAB 50000
#define NTD 8192
#define NBU 8191
#define LBU 4096
#define WSTR 68     // padded stride for weight matrices in shared
#define PBLK 128    // persistent tree-kernel blocks (64 td + 64 bu)

// ---------------- device scratch (static allocations only) ----------------
__device__ float g_ET_td[(size_t)VOCAB * HDIM];   // E_td transposed: (V, H)
__device__ float g_ET_bu[(size_t)VOCAB * HDIM];
__device__ float g_zx_td[NTD * HDIM];
__device__ float g_rx_td[NTD * HDIM];
__device__ float g_hx_td[NTD * HDIM];
__device__ float g_zx_bu[NBU * HDIM];
__device__ float g_rx_bu[NBU * HDIM];
__device__ float g_hx_bu[NBU * HDIM];
__device__ float g_h_td[(NTD + 1) * HDIM];
__device__ float g_h_bu[NBU * HDIM];
__device__ float g_tdmax[64 * HDIM];
__device__ int   g_bar_td[16];        // per-level barrier counters (zeroed by k_transpose)
__device__ int   g_bar_bu[16];

// ---------------- fast activations (ex2/rcp approx; abs err ~1e-6) ----------------
__device__ __forceinline__ float fex2(float x) { float r; asm("ex2.approx.f32 %0,%1;" : "=f"(r) : "f"(x)); return r; }
__device__ __forceinline__ float frcp(float x) { float r; asm("rcp.approx.f32 %0,%1;" : "=f"(r) : "f"(x)); return r; }
__device__ __forceinline__ float sigmf(float x) { return frcp(1.0f + fex2(-1.4426950408889634f * x)); }
__device__ __forceinline__ float tanhf_fast(float x) { return 2.0f * sigmf(2.0f * x) - 1.0f; }

// 64-participant release/acquire global barrier (thread 0 spins)
__device__ __forceinline__ void gbar64(int* ctr) {
    __syncthreads();
    if (threadIdx.x == 0) {
        unsigned long long g;
        asm volatile("cvta.to.global.u64 %0, %1;" : "=l"(g) : "l"(ctr));
        asm volatile("red.release.gpu.global.add.u32 [%0], 1;" :: "l"(g) : "memory");
        int v;
        do {
            asm volatile("ld.acquire.gpu.global.u32 %0, [%1];" : "=r"(v) : "l"(g) : "memory");
        } while (v < 64);
    }
    __syncthreads();
}

// ---------------- kernel 1: transpose E (H,V) -> ET (V,H), reset barriers, zero td root ----------------
__global__ void k_transpose(const float* __restrict__ E_td, const float* __restrict__ E_bu) {
    __shared__ float tile[64][33];
    const float* E = (blockIdx.y == 0) ? E_td : E_bu;
    float* ET = (blockIdx.y == 0) ? g_ET_td : g_ET_bu;
    int v0 = blockIdx.x * 32;
#pragma unroll
    for (int it = 0; it < 8; it++) {
        int e = it * 256 + threadIdx.x;
        int h = e >> 5, vi = e & 31;
        int v = v0 + vi;
        tile[h][vi] = (v < VOCAB) ? E[(size_t)h * VOCAB + v] : 0.f;
    }
    __syncthreads();
#pragma unroll
    for (int it = 0; it < 8; it++) {
        int e = it * 256 + threadIdx.x;
        int vi = e >> 6, h = e & 63;
        int v = v0 + vi;
        if (v < VOCAB) ET[v * 64 + h] = tile[h][vi];
    }
    if (blockIdx.x == 0 && blockIdx.y == 0) {
        if (threadIdx.x < 64) g_h_td[threadIdx.x] = 0.f;           // node_h[0] = 0
        else if (threadIdx.x < 80) g_bar_td[threadIdx.x - 64] = 0; // reset barriers
        else if (threadIdx.x < 96) g_bar_bu[threadIdx.x - 80] = 0;
    }
}

// ---------------- kernel 2: fused embedding gather + gate pre-activations ----------------
// 2 nodes per slot: halves W LDS traffic, doubles gather MLP
__global__ void __launch_bounds__(256) k_embed(
    const float* __restrict__ word_td, const int* __restrict__ idx_td,
    const float* __restrict__ word_bu, const int* __restrict__ idx_bu,
    const float* __restrict__ Wz_td, const float* __restrict__ Wr_td, const float* __restrict__ Wh_td,
    const float* __restrict__ bz_td, const float* __restrict__ br_td, const float* __restrict__ bh_td,
    const float* __restrict__ Wz_bu, const float* __restrict__ Wr_bu, const float* __restrict__ Wh_bu,
    const float* __restrict__ bz_bu, const float* __restrict__ br_bu, const float* __restrict__ bh_bu,
    int nblk)
{
    extern __shared__ float sm[];
    float* sW = sm;                       // 3 * 64 * WSTR  (transposed: sW[g][k*WSTR + h])
    float* sb = sW + 3 * 64 * WSTR;       // 3 * 64
    float* sWord = sb + 192;              // 32 * 64
    float* sXe = sWord + 2048;            // 32 * 64
    int* sIdx = (int*)(sXe + 2048);       // 32 * 64

    bool is_td = (blockIdx.x < nblk);
    const float* word = is_td ? word_td : word_bu;
    const int* idx = is_td ? idx_td : idx_bu;
    const float* ET = is_td ? g_ET_td : g_ET_bu;
    const float* Wz = is_td ? Wz_td : Wz_bu;
    const float* Wr = is_td ? Wr_td : Wr_bu;
    const float* Wh = is_td ? Wh_td : Wh_bu;
    const float* bz = is_td ? bz_td : bz_bu;
    const float* br = is_td ? br_td : br_bu;
    const float* bh = is_td ? bh_td : bh_bu;
    float* zx = is_td ? g_zx_td : g_zx_bu;
    float* rx = is_td ? g_rx_td : g_rx_bu;
    float* hx = is_td ? g_hx_td : g_hx_bu;
    int nNodes = is_td ? NTD : NBU;

    for (int g = 0; g < 3; g++) {
        const float* Wg = (g == 0) ? Wz : (g == 1) ? Wr : Wh;
        for (int e = threadIdx.x; e < 4096; e += 256) {
            int hh = e >> 6, kk = e & 63;
            sW[g * 64 * WSTR + kk * WSTR + hh] = Wg[e];
        }
    }
    if (threadIdx.x < 64) sb[threadIdx.x] = bz[threadIdx.x];
    else if (threadIdx.x < 128) sb[threadIdx.x] = br[threadIdx.x - 64];
    else if (threadIdx.x < 192) sb[threadIdx.x] = bh[threadIdx.x - 128];
    __syncthreads();

    int slot = threadIdx.x >> 4;    // 0..15
    int t = threadIdx.x & 15;
    int h4 = t * 4;
    int blkBr = is_td ? blockIdx.x : blockIdx.x - nblk;

    for (int base = blkBr * 32; base < nNodes; base += nblk * 32) {
        int n0 = base + slot;
        int n1 = base + slot + 16;
        bool a0 = (n0 < nNodes), a1 = (n1 < nNodes);
        if (a0) {
            *(int4*)&sIdx[slot * 64 + h4] = *(const int4*)&idx[n0 * 64 + h4];
            *(float4*)&sWord[slot * 64 + h4] = *(const float4*)&word[n0 * 64 + h4];
        }
        if (a1) {
            *(int4*)&sIdx[(slot + 16) * 64 + h4] = *(const int4*)&idx[n1 * 64 + h4];
            *(float4*)&sWord[(slot + 16) * 64 + h4] = *(const float4*)&word[n1 * 64 + h4];
        }
        __syncthreads();
        float4 acc0 = make_float4(0.f, 0.f, 0.f, 0.f);
        float4 acc1 = make_float4(0.f, 0.f, 0.f, 0.f);
        {
            const int* ip0 = &sIdx[slot * 64];
            const float* wp0 = &sWord[slot * 64];
            const int* ip1 = &sIdx[(slot + 16) * 64];
            const float* wp1 = &sWord[(slot + 16) * 64];
#pragma unroll 4
            for (int w = 0; w < 64; w++) {
                if (a0) {
                    float4 e4 = *(const float4*)&ET[ip0[w] * 64 + h4];
                    float wv = wp0[w];
                    acc0.x += e4.x * wv; acc0.y += e4.y * wv;
                    acc0.z += e4.z * wv; acc0.w += e4.w * wv;
                }
                if (a1) {
                    float4 e4 = *(const float4*)&ET[ip1[w] * 64 + h4];
                    float wv = wp1[w];
                    acc1.x += e4.x * wv; acc1.y += e4.y * wv;
                    acc1.z += e4.z * wv; acc1.w += e4.w * wv;
                }
            }
        }
        *(float4*)&sXe[slot * 64 + h4] = acc0;
        *(float4*)&sXe[(slot + 16) * 64 + h4] = acc1;
        __syncthreads();
        {
            const float* xe0 = &sXe[slot * 64];
            const float* xe1 = &sXe[(slot + 16) * 64];
            float4 bzv = *(const float4*)&sb[0 * 64 + h4];
            float4 brv = *(const float4*)&sb[1 * 64 + h4];
            float4 bhv = *(const float4*)&sb[2 * 64 + h4];
            float4 az0 = bzv, ar0 = brv, ah0 = bhv;
            float4 az1 = bzv, ar1 = brv, ah1 = bhv;
#pragma unroll 4
            for (int k = 0; k < 64; k++) {
                float4 wz4 = *(const float4*)&sW[0 * 64 * WSTR + k * WSTR + h4];
                float4 wr4 = *(const float4*)&sW[1 * 64 * WSTR + k * WSTR + h4];
                float4 wh4 = *(const float4*)&sW[2 * 64 * WSTR + k * WSTR + h4];
                float x0 = xe0[k], x1 = xe1[k];
                az0.x += wz4.x * x0; az0.y += wz4.y * x0; az0.z += wz4.z * x0; az0.w += wz4.w * x0;
                ar0.x += wr4.x * x0; ar0.y += wr4.y * x0; ar0.z += wr4.z * x0; ar0.w += wr4.w * x0;
                ah0.x += wh4.x * x0; ah0.y += wh4.y * x0; ah0.z += wh4.z * x0; ah0.w += wh4.w * x0;
                az1.x += wz4.x * x1; az1.y += wz4.y * x1; az1.z += wz4.z * x1; az1.w += wz4.w * x1;
                ar1.x += wr4.x * x1; ar1.y += wr4.y * x1; ar1.z += wr4.z * x1; ar1.w += wr4.w * x1;
                ah1.x += wh4.x * x1; ah1.y += wh4.y * x1; ah1.z += wh4.z * x1; ah1.w += wh4.w * x1;
            }
#pragma unroll
            for (int p = 0; p < 2; p++) {
                int n = p ? n1 : n0;
                bool act = p ? a1 : a0;
                float4 az = p ? az1 : az0, ar = p ? ar1 : ar0, ah = p ? ah1 : ah0;
                if (!act) continue;
                if (is_td || n >= LBU) {
                    *(float4*)&zx[n * 64 + h4] = az;
                    *(float4*)&rx[n * 64 + h4] = ar;
                    *(float4*)&hx[n * 64 + h4] = ah;
                } else {
                    float4 lh;
                    lh.x = (1.f - sigmf(az.x)) * tanhf_fast(ah.x);
                    lh.y = (1.f - sigmf(az.y)) * tanhf_fast(ah.y);
                    lh.z = (1.f - sigmf(az.z)) * tanhf_fast(ah.z);
                    lh.w = (1.f - sigmf(az.w)) * tanhf_fast(ah.w);
                    *(float4*)&g_h_bu[n * 64 + h4] = lh;
                }
            }
        }
        __syncthreads();
    }
}

// ---------------- kernel 3: persistent tree — td chain (blocks 0..63) || bu chain (blocks 64..127) ----------------
__global__ void __launch_bounds__(256) k_tree(
    const float* __restrict__ Uz_td, const float* __restrict__ Ur_td, const float* __restrict__ Uh_td,
    const float* __restrict__ Uz_bu, const float* __restrict__ Ur_bu, const float* __restrict__ Uh_bu)
{
    extern __shared__ float sm[];
    float* sU = sm;                       // 3 * 64 * WSTR (own chain only)
    float* sHp = sU + 3 * 64 * WSTR;      // 16 * 64
    float* sHr = sHp + 1024;              // 16 * 64

    bool is_td = (blockIdx.x < 64);
    int gid = is_td ? blockIdx.x : blockIdx.x - 64;

    const float* Uz = is_td ? Uz_td : Uz_bu;
    const float* Ur = is_td ? Ur_td : Ur_bu;
    const float* Uh = is_td ? Uh_td : Uh_bu;
    const float* gz = is_td ? g_zx_td : g_zx_bu;
    const float* gr = is_td ? g_rx_td : g_rx_bu;
    const float* gh = is_td ? g_hx_td : g_hx_bu;

    for (int g = 0; g < 3; g++) {
        const float* Ug = (g == 0) ? Uz : (g == 1) ? Ur : Uh;
        for (int e = threadIdx.x; e < 4096; e += 256) {
            int hh = e >> 6, kk = e & 63;
            sU[g * 64 * WSTR + kk * WSTR + hh] = Ug[e];
        }
    }
    __syncthreads();

    int slot = threadIdx.x >> 4;
    int t = threadIdx.x & 15;
    int h4 = t * 4;

    const int S = is_td ? 13 : 12;
    int* bar = is_td ? g_bar_td : g_bar_bu;

    // gate index for (level, row): td: gi = lo + r - 1 ; bu: gi = LBU + lo + r
    // prefetch gates for level 1, tile gid
    float4 paz, par, pah;
    bool pv = false;
    {
        int s2 = 1;
        int cnt2 = is_td ? 2 : (1 << (12 - s2));
        int lo2 = is_td ? ((1 << s2) - 1) : (4096 - (1 << (13 - s2)));
        int r = gid * 16 + slot;
        if (r < cnt2) {
            int gi = is_td ? (lo2 + r - 1) : (LBU + lo2 + r);
            paz = *(const float4*)&gz[gi * 64 + h4];
            par = *(const float4*)&gr[gi * 64 + h4];
            pah = *(const float4*)&gh[gi * 64 + h4];
            pv = true;
        }
    }

    for (int s = 1; s <= S; s++) {
        int cnt, lo;
        if (is_td) { lo = (1 << s) - 1; cnt = (s < 13) ? (1 << s) : 2; }
        else       { cnt = 1 << (12 - s); lo = 4096 - (1 << (13 - s)); }
        int tiles = (cnt + 15) >> 4;

        for (int tile = gid; tile < tiles; tile += 64) {
            int r = tile * 16 + slot;
            bool act = (r < cnt);
            float4 hp = make_float4(0.f, 0.f, 0.f, 0.f);
            float4 az, ar, ah;
            int outRow = 0;
            if (act) {
                int gi;
                if (is_td) {
                    int o = lo + r;
                    gi = o - 1;
                    hp = *(const float4*)&g_h_td[((o - 1) >> 1) * 64 + h4];
                    outRow = o;
                } else {
                    int j = lo + r;
                    gi = LBU + j;
                    float4 a = *(const float4*)&g_h_bu[(2 * j) * 64 + h4];
                    float4 b = *(const float4*)&g_h_bu[(2 * j + 1) * 64 + h4];
                    hp = make_float4(a.x + b.x, a.y + b.y, a.z + b.z, a.w + b.w);
                    outRow = gi;
                }
                if (tile == gid && pv) { az = paz; ar = par; ah = pah; }
                else {
                    az = *(const float4*)&gz[gi * 64 + h4];
                    ar = *(const float4*)&gr[gi * 64 + h4];
                    ah = *(const float4*)&gh[gi * 64 + h4];
                }
            }
            *(float4*)&sHp[slot * 64 + h4] = hp;
            __syncthreads();
            float4 z = make_float4(0, 0, 0, 0), rr = make_float4(0, 0, 0, 0);
            if (act) {
                float4 mz = az, mr = ar;
                const float* hpv = &sHp[slot * 64];
#pragma unroll 4
                for (int k = 0; k < 64; k++) {
                    float x = hpv[k];
                    float4 uz4 = *(const float4*)&sU[0 * 64 * WSTR + k * WSTR + h4];
                    float4 ur4 = *(const float4*)&sU[1 * 64 * WSTR + k * WSTR + h4];
                    mz.x += uz4.x * x; mz.y += uz4.y * x; mz.z += uz4.z * x; mz.w += uz4.w * x;
                    mr.x += ur4.x * x; mr.y += ur4.y * x; mr.z += ur4.z * x; mr.w += ur4.w * x;
                }
                z = make_float4(sigmf(mz.x), sigmf(mz.y), sigmf(mz.z), sigmf(mz.w));
                rr = make_float4(sigmf(mr.x), sigmf(mr.y), sigmf(mr.z), sigmf(mr.w));
            }
            float4 hr = make_float4(hp.x * rr.x, hp.y * rr.y, hp.z * rr.z, hp.w * rr.w);
            *(float4*)&sHr[slot * 64 + h4] = act ? hr : make_float4(0, 0, 0, 0);
            __syncthreads();
            if (act) {
                float4 mh = ah;
                const float* hrv = &sHr[slot * 64];
#pragma unroll 4
                for (int k = 0; k < 64; k++) {
                    float x = hrv[k];
                    float4 uh4 = *(const float4*)&sU[2 * 64 * WSTR + k * WSTR + h4];
                    mh.x += uh4.x * x; mh.y += uh4.y * x; mh.z += uh4.z * x; mh.w += uh4.w * x;
                }
                float4 c = make_float4(tanhf_fast(mh.x), tanhf_fast(mh.y), tanhf_fast(mh.z), tanhf_fast(mh.w));
                float4 hn;
                hn.x = z.x * hp.x + (1.f - z.x) * c.x;
                hn.y = z.y * hp.y + (1.f - z.y) * c.y;
                hn.z = z.z * hp.z + (1.f - z.z) * c.z;
                hn.w = z.w * hp.w + (1.f - z.w) * c.w;
                if (is_td) *(float4*)&g_h_td[outRow * 64 + h4] = hn;
                else       *(float4*)&g_h_bu[outRow * 64 + h4] = hn;
            }
            __syncthreads();
        }

        // prefetch gates for next level (independent of barrier) then barrier
        pv = false;
        if (s < S) {
            int s2 = s + 1;
            int cnt2, lo2;
            if (is_td) { lo2 = (1 << s2) - 1; cnt2 = (s2 < 13) ? (1 << s2) : 2; }
            else       { cnt2 = 1 << (12 - s2); lo2 = 4096 - (1 << (13 - s2)); }
            int r = gid * 16 + slot;
            if (r < cnt2) {
                int gi = is_td ? (lo2 + r - 1) : (LBU + lo2 + r);
                paz = *(const float4*)&gz[gi * 64 + h4];
                par = *(const float4*)&gr[gi * 64 + h4];
                pah = *(const float4*)&gh[gi * 64 + h4];
                pv = true;
            }
        }
        if (is_td || s < S) gbar64(&bar[s]);   // bu chain skips final barrier (kernel end syncs)
    }

    // td group: partial max over leaf rows 4096..8192 (64 blocks exactly)
    if (is_td && threadIdx.x < 64) {
        int h = threadIdx.x;
        float m = -1e30f;
        for (int r = 4096 + gid; r <= NTD; r += 64)
            m = fmaxf(m, g_h_td[r * 64 + h]);
        g_tdmax[gid * 64 + h] = m;
    }
}

// ---------------- kernel 4: head (max-reduce + MLP + softmax) ----------------
__global__ void k_final(const float* __restrict__ W1, const float* __restrict__ b1,
                        const float* __restrict__ W4, const float* __restrict__ b4,
                        float* __restrict__ out) {
    __shared__ float fs[128], f1[64], lg[4];
    int tid = threadIdx.x;  // 128 threads
    if (tid < 64) {
        float m = -1e30f;
        for (int b = 0; b < 64; b++) m = fmaxf(m, g_tdmax[b * 64 + tid]);
        fs[tid] = m;
    } else {
        fs[tid] = g_h_bu[(NBU - 1) * 64 + (tid - 64)];
    }
    __syncthreads();
    if (tid < 64) {
        float a = b1[tid];
#pragma unroll 4
        for (int k = 0; k < 128; k++) a += W1[tid * 128 + k] * fs[k];
        f1[tid] = fmaxf(a, 0.f);
    }
    __syncthreads();
    if (tid < 4) {
        float a = b4[tid];
        for (int k = 0; k < 64; k++) a += W4[tid * 64 + k] * f1[k];
        lg[tid] = a;
    }
    __syncthreads();
    if (tid == 0) {
        float mx = fmaxf(fmaxf(lg[0], lg[1]), fmaxf(lg[2], lg[3]));
        float e0 = expf(lg[0] - mx), e1 = expf(lg[1] - mx);
        float e2 = expf(lg[2] - mx), e3 = expf(lg[3] - mx);
        float s = e0 + e1 + e2 + e3;
        out[0] = e0 / s; out[1] = e1 / s; out[2] = e2 / s; out[3] = e3 / s;
    }
}

// ---------------- launch ----------------
extern "C" void kernel_launch(void* const* d_in, const int* in_sizes, int n_in,
                              void* d_out, int out_size) {
    const float* td_x_word = (const float*)d_in[0];
    const float* bu_x_word = (const float*)d_in[1];
    const float* E_td  = (const float*)d_in[2];
    const float* Wz_td = (const float*)d_in[3];
    const float* Uz_td = (const float*)d_in[4];
    const float* bz_td = (const float*)d_in[5];
    const float* Wr_td = (const float*)d_in[6];
    const float* Ur_td = (const float*)d_in[7];
    const float* br_td = (const float*)d_in[8];
    const float* Wh_td = (const float*)d_in[9];
    const float* Uh_td = (const float*)d_in[10];
    const float* bh_td = (const float*)d_in[11];
    const float* E_bu  = (const float*)d_in[12];
    const float* Wz_bu = (const float*)d_in[13];
    const float* Uz_bu = (const float*)d_in[14];
    const float* bz_bu = (const float*)d_in[15];
    const float* Wr_bu = (const float*)d_in[16];
    const float* Ur_bu = (const float*)d_in[17];
    const float* br_bu = (const float*)d_in[18];
    const float* Wh_bu = (const float*)d_in[19];
    const float* Uh_bu = (const float*)d_in[20];
    const float* bh_bu = (const float*)d_in[21];
    const float* W1 = (const float*)d_in[22];
    const float* b1 = (const float*)d_in[23];
    const float* W4 = (const float*)d_in[24];
    const float* b4 = (const float*)d_in[25];

    const int* idx_td = (const int*)d_in[26];
    const int* idx_bu = (const int*)d_in[27];
    for (int i = 26; i < n_in; i++) {
        if (in_sizes[i] == NTD * 64) idx_td = (const int*)d_in[i];
        else if (in_sizes[i] == NBU * 64) idx_bu = (const int*)d_in[i];
    }

    const int smemE = (3 * 64 * WSTR + 192 + 2048 + 2048 + 2048) * 4;
    const int smemT = (3 * 64 * WSTR + 1024 + 1024) * 4;
    cudaFuncSetAttribute(k_embed, cudaFuncAttributeMaxDynamicSharedMemorySize, smemE);
    cudaFuncSetAttribute(k_tree, cudaFuncAttributeMaxDynamicSharedMemorySize, smemT);

    k_transpose<<<dim3((VOCAB + 31) / 32, 2), 256>>>(E_td, E_bu);

    const int NBLK = 148;
    k_embed<<<2 * NBLK, 256, smemE>>>(td_x_word, idx_td, bu_x_word, idx_bu,
                                      Wz_td, Wr_td, Wh_td, bz_td, br_td, bh_td,
                                      Wz_bu, Wr_bu, Wh_bu, bz_bu, br_bu, bh_bu, NBLK);

    k_tree<<<PBLK, 256, smemT>>>(Uz_td, Ur_td, Uh_td, Uz_bu, Ur_bu, Uh_bu);

    k_final<<<1, 128>>>(W1, b1, W4, b4, (float*)d_out);
}

// round 7
// speedup vs baseline: 1.2962x; 1.0083x over previous
#include <cuda_runtime.h>
#include <math.h>

#define HDIM 64
#define VOCAB 50000
#define NTD 8192
#define NBU 8191
#define LBU 4096
#define WSTR 68     // padded stride for weight matrices in shared
#define PBLK 128    // persistent tree-kernel blocks (64 td + 64 bu)

// ---------------- device scratch (static allocations only) ----------------
__device__ float g_ET_td[(size_t)VOCAB * HDIM];   // E_td transposed: (V, H)
__device__ float g_ET_bu[(size_t)VOCAB * HDIM];
__device__ float g_zx_td[NTD * HDIM];
__device__ float g_rx_td[NTD * HDIM];
__device__ float g_hx_td[NTD * HDIM];
__device__ float g_zx_bu[NBU * HDIM];
__device__ float g_rx_bu[NBU * HDIM];
__device__ float g_hx_bu[NBU * HDIM];
__device__ float g_h_td[(NTD + 1) * HDIM];
__device__ float g_h_bu[NBU * HDIM];
__device__ float g_tdmax[64 * HDIM];
__device__ int   g_bar_td[16];        // per-level barrier counters (zeroed by k_transpose)
__device__ int   g_bar_bu[16];

// ---------------- fast activations (ex2/rcp approx; abs err ~1e-6) ----------------
__device__ __forceinline__ float fex2(float x) { float r; asm("ex2.approx.f32 %0,%1;" : "=f"(r) : "f"(x)); return r; }
__device__ __forceinline__ float frcp(float x) { float r; asm("rcp.approx.f32 %0,%1;" : "=f"(r) : "f"(x)); return r; }
__device__ __forceinline__ float sigmf(float x) { return frcp(1.0f + fex2(-1.4426950408889634f * x)); }
__device__ __forceinline__ float tanhf_fast(float x) { return 2.0f * sigmf(2.0f * x) - 1.0f; }

// global barrier: arrive (release); optionally spin until count==target (acquire)
__device__ __forceinline__ void gbar(int* ctr, int target, bool wait) {
    __syncthreads();
    if (threadIdx.x == 0) {
        unsigned long long g;
        asm volatile("cvta.to.global.u64 %0, %1;" : "=l"(g) : "l"(ctr));
        asm volatile("red.release.gpu.global.add.u32 [%0], 1;" :: "l"(g) : "memory");
        if (wait) {
            int v;
            do {
                asm volatile("ld.acquire.gpu.global.u32 %0, [%1];" : "=r"(v) : "l"(g) : "memory");
            } while (v < target);
        }
    }
    __syncthreads();
}

// ---------------- kernel 1: transpose E (H,V) -> ET (V,H), reset barriers, zero td root ----------------
__global__ void __launch_bounds__(256) k_transpose(const float* __restrict__ E_td, const float* __restrict__ E_bu) {
    __shared__ float tile[64][65];
    const float* E = (blockIdx.y == 0) ? E_td : E_bu;
    float* ET = (blockIdx.y == 0) ? g_ET_td : g_ET_bu;
    int v0 = blockIdx.x * 64;
    int rem = VOCAB - v0;              // 64 normally; 16 for the last block (50000 = 781*64 + 16)
#pragma unroll
    for (int it = 0; it < 4; it++) {
        int e = it * 256 + threadIdx.x;       // 0..1023
        int h = e >> 4;                        // 0..63
        int c = (e & 15) * 4;                  // 0..60
        if (c < rem) {
            float4 v = *(const float4*)&E[(size_t)h * VOCAB + v0 + c];
            tile[h][c + 0] = v.x; tile[h][c + 1] = v.y;
            tile[h][c + 2] = v.z; tile[h][c + 3] = v.w;
        }
    }
    __syncthreads();
#pragma unroll
    for (int it = 0; it < 4; it++) {
        int e = it * 256 + threadIdx.x;
        int v = e >> 4;                        // 0..63
        int c = (e & 15) * 4;                  // h base
        if (v < rem) {
            float4 val = make_float4(tile[c][v], tile[c + 1][v], tile[c + 2][v], tile[c + 3][v]);
            *(float4*)&ET[(size_t)(v0 + v) * 64 + c] = val;
        }
    }
    if (blockIdx.x == 0 && blockIdx.y == 0) {
        if (threadIdx.x < 64) g_h_td[threadIdx.x] = 0.f;           // node_h[0] = 0
        else if (threadIdx.x < 80) g_bar_td[threadIdx.x - 64] = 0; // reset barriers
        else if (threadIdx.x < 96) g_bar_bu[threadIdx.x - 80] = 0;
    }
}

// ---------------- kernel 2: fused embedding gather + gate pre-activations ----------------
__global__ void __launch_bounds__(256) k_embed(
    const float* __restrict__ word_td, const int* __restrict__ idx_td,
    const float* __restrict__ word_bu, const int* __restrict__ idx_bu,
    const float* __restrict__ Wz_td, const float* __restrict__ Wr_td, const float* __restrict__ Wh_td,
    const float* __restrict__ bz_td, const float* __restrict__ br_td, const float* __restrict__ bh_td,
    const float* __restrict__ Wz_bu, const float* __restrict__ Wr_bu, const float* __restrict__ Wh_bu,
    const float* __restrict__ bz_bu, const float* __restrict__ br_bu, const float* __restrict__ bh_bu,
    int nblk)
{
    extern __shared__ float sm[];
    float* sW = sm;                       // 3 * 64 * WSTR  (transposed: sW[g][k*WSTR + h])
    float* sb = sW + 3 * 64 * WSTR;       // 3 * 64
    float* sWord = sb + 192;              // 32 * 64
    float* sXe = sWord + 2048;            // 32 * 64
    int* sIdx = (int*)(sXe + 2048);       // 32 * 64

    bool is_td = (blockIdx.x < nblk);
    const float* word = is_td ? word_td : word_bu;
    const int* idx = is_td ? idx_td : idx_bu;
    const float* ET = is_td ? g_ET_td : g_ET_bu;
    const float* Wz = is_td ? Wz_td : Wz_bu;
    const float* Wr = is_td ? Wr_td : Wr_bu;
    const float* Wh = is_td ? Wh_td : Wh_bu;
    const float* bz = is_td ? bz_td : bz_bu;
    const float* br = is_td ? br_td : br_bu;
    const float* bh = is_td ? bh_td : bh_bu;
    float* zx = is_td ? g_zx_td : g_zx_bu;
    float* rx = is_td ? g_rx_td : g_rx_bu;
    float* hx = is_td ? g_hx_td : g_hx_bu;
    int nNodes = is_td ? NTD : NBU;

    for (int g = 0; g < 3; g++) {
        const float* Wg = (g == 0) ? Wz : (g == 1) ? Wr : Wh;
        for (int e = threadIdx.x; e < 4096; e += 256) {
            int hh = e >> 6, kk = e & 63;
            sW[g * 64 * WSTR + kk * WSTR + hh] = Wg[e];
        }
    }
    if (threadIdx.x < 64) sb[threadIdx.x] = bz[threadIdx.x];
    else if (threadIdx.x < 128) sb[threadIdx.x] = br[threadIdx.x - 64];
    else if (threadIdx.x < 192) sb[threadIdx.x] = bh[threadIdx.x - 128];
    __syncthreads();

    int slot = threadIdx.x >> 4;    // 0..15
    int t = threadIdx.x & 15;
    int h4 = t * 4;
    int blkBr = is_td ? blockIdx.x : blockIdx.x - nblk;

    for (int base = blkBr * 32; base < nNodes; base += nblk * 32) {
        int n0 = base + slot;
        int n1 = base + slot + 16;
        bool a0 = (n0 < nNodes), a1 = (n1 < nNodes);
        if (a0) {
            *(int4*)&sIdx[slot * 64 + h4] = *(const int4*)&idx[n0 * 64 + h4];
            *(float4*)&sWord[slot * 64 + h4] = *(const float4*)&word[n0 * 64 + h4];
        }
        if (a1) {
            *(int4*)&sIdx[(slot + 16) * 64 + h4] = *(const int4*)&idx[n1 * 64 + h4];
            *(float4*)&sWord[(slot + 16) * 64 + h4] = *(const float4*)&word[n1 * 64 + h4];
        }
        __syncthreads();
        float4 acc0 = make_float4(0.f, 0.f, 0.f, 0.f);
        float4 acc1 = make_float4(0.f, 0.f, 0.f, 0.f);
        {
            const int* ip0 = &sIdx[slot * 64];
            const float* wp0 = &sWord[slot * 64];
            const int* ip1 = &sIdx[(slot + 16) * 64];
            const float* wp1 = &sWord[(slot + 16) * 64];
#pragma unroll 4
            for (int w = 0; w < 64; w++) {
                if (a0) {
                    float4 e4 = *(const float4*)&ET[ip0[w] * 64 + h4];
                    float wv = wp0[w];
                    acc0.x += e4.x * wv; acc0.y += e4.y * wv;
                    acc0.z += e4.z * wv; acc0.w += e4.w * wv;
                }
                if (a1) {
                    float4 e4 = *(const float4*)&ET[ip1[w] * 64 + h4];
                    float wv = wp1[w];
                    acc1.x += e4.x * wv; acc1.y += e4.y * wv;
                    acc1.z += e4.z * wv; acc1.w += e4.w * wv;
                }
            }
        }
        *(float4*)&sXe[slot * 64 + h4] = acc0;
        *(float4*)&sXe[(slot + 16) * 64 + h4] = acc1;
        __syncthreads();
        {
            const float* xe0 = &sXe[slot * 64];
            const float* xe1 = &sXe[(slot + 16) * 64];
            float4 bzv = *(const float4*)&sb[0 * 64 + h4];
            float4 brv = *(const float4*)&sb[1 * 64 + h4];
            float4 bhv = *(const float4*)&sb[2 * 64 + h4];
            float4 az0 = bzv, ar0 = brv, ah0 = bhv;
            float4 az1 = bzv, ar1 = brv, ah1 = bhv;
#pragma unroll 4
            for (int k = 0; k < 64; k++) {
                float4 wz4 = *(const float4*)&sW[0 * 64 * WSTR + k * WSTR + h4];
                float4 wr4 = *(const float4*)&sW[1 * 64 * WSTR + k * WSTR + h4];
                float4 wh4 = *(const float4*)&sW[2 * 64 * WSTR + k * WSTR + h4];
                float x0 = xe0[k], x1 = xe1[k];
                az0.x += wz4.x * x0; az0.y += wz4.y * x0; az0.z += wz4.z * x0; az0.w += wz4.w * x0;
                ar0.x += wr4.x * x0; ar0.y += wr4.y * x0; ar0.z += wr4.z * x0; ar0.w += wr4.w * x0;
                ah0.x += wh4.x * x0; ah0.y += wh4.y * x0; ah0.z += wh4.z * x0; ah0.w += wh4.w * x0;
                az1.x += wz4.x * x1; az1.y += wz4.y * x1; az1.z += wz4.z * x1; az1.w += wz4.w * x1;
                ar1.x += wr4.x * x1; ar1.y += wr4.y * x1; ar1.z += wr4.z * x1; ar1.w += wr4.w * x1;
                ah1.x += wh4.x * x1; ah1.y += wh4.y * x1; ah1.z += wh4.z * x1; ah1.w += wh4.w * x1;
            }
#pragma unroll
            for (int p = 0; p < 2; p++) {
                int n = p ? n1 : n0;
                bool act = p ? a1 : a0;
                float4 az = p ? az1 : az0, ar = p ? ar1 : ar0, ah = p ? ah1 : ah0;
                if (!act) continue;
                if (is_td || n >= LBU) {
                    *(float4*)&zx[n * 64 + h4] = az;
                    *(float4*)&rx[n * 64 + h4] = ar;
                    *(float4*)&hx[n * 64 + h4] = ah;
                } else {
                    float4 lh;
                    lh.x = (1.f - sigmf(az.x)) * tanhf_fast(ah.x);
                    lh.y = (1.f - sigmf(az.y)) * tanhf_fast(ah.y);
                    lh.z = (1.f - sigmf(az.z)) * tanhf_fast(ah.z);
                    lh.w = (1.f - sigmf(az.w)) * tanhf_fast(ah.w);
                    *(float4*)&g_h_bu[n * 64 + h4] = lh;
                }
            }
        }
        __syncthreads();
    }
}

// ---------------- GRU for one 16-node tile (called by all 256 threads) ----------------
__device__ __forceinline__ void gru_tile(
    bool is_td, int lo, int cnt, int tile,
    const float* __restrict__ gz, const float* __restrict__ gr, const float* __restrict__ gh,
    const float* sU, float* sHp, float* sHr, int slot, int h4)
{
    int r = tile * 16 + slot;
    bool act = (r < cnt);
    float4 hp = make_float4(0.f, 0.f, 0.f, 0.f);
    float4 az, ar, ah;
    int outRow = 0;
    if (act) {
        int gi;
        if (is_td) {
            int o = lo + r;
            gi = o - 1;
            hp = *(const float4*)&g_h_td[((o - 1) >> 1) * 64 + h4];
            outRow = o;
        } else {
            int j = lo + r;
            gi = LBU + j;
            float4 a = *(const float4*)&g_h_bu[(2 * j) * 64 + h4];
            float4 b = *(const float4*)&g_h_bu[(2 * j + 1) * 64 + h4];
            hp = make_float4(a.x + b.x, a.y + b.y, a.z + b.z, a.w + b.w);
            outRow = gi;
        }
        az = *(const float4*)&gz[gi * 64 + h4];
        ar = *(const float4*)&gr[gi * 64 + h4];
        ah = *(const float4*)&gh[gi * 64 + h4];
    }
    *(float4*)&sHp[slot * 64 + h4] = hp;
    __syncthreads();
    float4 z = make_float4(0, 0, 0, 0), rr = make_float4(0, 0, 0, 0);
    if (act) {
        float4 mz = az, mr = ar;
        const float* hpv = &sHp[slot * 64];
#pragma unroll 4
        for (int k = 0; k < 64; k++) {
            float x = hpv[k];
            float4 uz4 = *(const float4*)&sU[0 * 64 * WSTR + k * WSTR + h4];
            float4 ur4 = *(const float4*)&sU[1 * 64 * WSTR + k * WSTR + h4];
            mz.x += uz4.x * x; mz.y += uz4.y * x; mz.z += uz4.z * x; mz.w += uz4.w * x;
            mr.x += ur4.x * x; mr.y += ur4.y * x; mr.z += ur4.z * x; mr.w += ur4.w * x;
        }
        z = make_float4(sigmf(mz.x), sigmf(mz.y), sigmf(mz.z), sigmf(mz.w));
        rr = make_float4(sigmf(mr.x), sigmf(mr.y), sigmf(mr.z), sigmf(mr.w));
    }
    float4 hr = make_float4(hp.x * rr.x, hp.y * rr.y, hp.z * rr.z, hp.w * rr.w);
    *(float4*)&sHr[slot * 64 + h4] = act ? hr : make_float4(0, 0, 0, 0);
    __syncthreads();
    if (act) {
        float4 mh = ah;
        const float* hrv = &sHr[slot * 64];
#pragma unroll 4
        for (int k = 0; k < 64; k++) {
            float x = hrv[k];
            float4 uh4 = *(const float4*)&sU[2 * 64 * WSTR + k * WSTR + h4];
            mh.x += uh4.x * x; mh.y += uh4.y * x; mh.z += uh4.z * x; mh.w += uh4.w * x;
        }
        float4 c = make_float4(tanhf_fast(mh.x), tanhf_fast(mh.y), tanhf_fast(mh.z), tanhf_fast(mh.w));
        float4 hn;
        hn.x = z.x * hp.x + (1.f - z.x) * c.x;
        hn.y = z.y * hp.y + (1.f - z.y) * c.y;
        hn.z = z.z * hp.z + (1.f - z.z) * c.z;
        hn.w = z.w * hp.w + (1.f - z.w) * c.w;
        if (is_td) *(float4*)&g_h_td[outRow * 64 + h4] = hn;
        else       *(float4*)&g_h_bu[outRow * 64 + h4] = hn;
    }
    __syncthreads();
}

// ---------------- kernel 3: persistent tree + head ----------------
// blocks 0..63: td chain (levels 1-6 solo by block 0, 7-13 parallel), tdmax, head (block 0)
// blocks 64..127: bu chain (levels 1-5 parallel, 6-12 solo by block 64)
__global__ void __launch_bounds__(256) k_tree(
    const float* __restrict__ Uz_td, const float* __restrict__ Ur_td, const float* __restrict__ Uh_td,
    const float* __restrict__ Uz_bu, const float* __restrict__ Ur_bu, const float* __restrict__ Uh_bu,
    const float* __restrict__ W1, const float* __restrict__ b1,
    const float* __restrict__ W4, const float* __restrict__ b4,
    float* __restrict__ out)
{
    extern __shared__ float sm[];
    float* sU = sm;                       // 3 * 64 * WSTR (own chain only)
    float* sHp = sU + 3 * 64 * WSTR;      // 16 * 64
    float* sHr = sHp + 1024;              // 16 * 64

    bool is_td = (blockIdx.x < 64);
    int gid = is_td ? blockIdx.x : blockIdx.x - 64;

    const float* Uz = is_td ? Uz_td : Uz_bu;
    const float* Ur = is_td ? Ur_td : Ur_bu;
    const float* Uh = is_td ? Uh_td : Uh_bu;
    const float* gz = is_td ? g_zx_td : g_zx_bu;
    const float* gr = is_td ? g_rx_td : g_rx_bu;
    const float* gh = is_td ? g_hx_td : g_hx_bu;

    for (int g = 0; g < 3; g++) {
        const float* Ug = (g == 0) ? Uz : (g == 1) ? Ur : Uh;
        for (int e = threadIdx.x; e < 4096; e += 256) {
            int hh = e >> 6, kk = e & 63;
            sU[g * 64 * WSTR + kk * WSTR + hh] = Ug[e];
        }
    }
    __syncthreads();

    int slot = threadIdx.x >> 4;
    int t = threadIdx.x & 15;
    int h4 = t * 4;

    if (is_td) {
        // levels 1..6 (2..64 nodes): solo by block 0, __syncthreads between levels
        if (gid == 0) {
            for (int s = 1; s <= 6; s++) {
                int lo = (1 << s) - 1, cnt = 1 << s;
                int tiles = (cnt + 15) >> 4;
                for (int tile = 0; tile < tiles; tile++)
                    gru_tile(true, lo, cnt, tile, gz, gr, gh, sU, sHp, sHr, slot, h4);
            }
        }
        gbar(&g_bar_td[0], 64, true);
        // levels 7..13: all 64 td blocks, per-level barrier
        for (int s = 7; s <= 13; s++) {
            int lo = (1 << s) - 1;
            int cnt = (s < 13) ? (1 << s) : 2;
            int tiles = (cnt + 15) >> 4;
            for (int tile = gid; tile < tiles; tile += 64)
                gru_tile(true, lo, cnt, tile, gz, gr, gh, sU, sHp, sHr, slot, h4);
            gbar(&g_bar_td[s - 6], 64, true);       // indices 1..7
        }
        // partial max over leaf rows 4096..8192
        if (threadIdx.x < 64) {
            int h = threadIdx.x;
            float m = -1e30f;
            for (int r = 4096 + gid; r <= NTD; r += 64)
                m = fmaxf(m, g_h_td[r * 64 + h]);
            g_tdmax[gid * 64 + h] = m;
        }
        // head barrier: 64 td blocks + bu block 0 = 65 arrivals; only td block 0 waits
        gbar(&g_bar_td[8], 65, gid == 0);

        if (gid == 0) {
            __shared__ float fs[128], f1[64], lg[4];
            int tid = threadIdx.x;
            if (tid < 64) {
                float m = -1e30f;
#pragma unroll 8
                for (int b = 0; b < 64; b++) m = fmaxf(m, g_tdmax[b * 64 + tid]);
                fs[tid] = m;
            } else if (tid < 128) {
                fs[tid] = g_h_bu[(NBU - 1) * 64 + (tid - 64)];
            }
            __syncthreads();
            // W1 (64x128): row = tid>>2, 4 threads per row, 32 k's each via float4
            {
                int row = tid >> 2, part = tid & 3;
                float s = 0.f;
#pragma unroll
                for (int i = 0; i < 8; i++) {
                    int k = part * 32 + i * 4;
                    float4 w = *(const float4*)&W1[row * 128 + k];
                    s += w.x * fs[k] + w.y * fs[k + 1] + w.z * fs[k + 2] + w.w * fs[k + 3];
                }
                s += __shfl_down_sync(0xffffffffu, s, 1);
                s += __shfl_down_sync(0xffffffffu, s, 2);
                if (part == 0) f1[row] = fmaxf(s + b1[row], 0.f);
            }
            __syncthreads();
            // W4 (4x64): warp w handles row w
            if (tid < 128) {
                int row = tid >> 5, lane = tid & 31;
                float s = W4[row * 64 + lane] * f1[lane] + W4[row * 64 + 32 + lane] * f1[32 + lane];
#pragma unroll
                for (int o = 16; o > 0; o >>= 1) s += __shfl_down_sync(0xffffffffu, s, o);
                if (lane == 0) lg[row] = s + b4[row];
            }
            __syncthreads();
            if (tid == 0) {
                float mx = fmaxf(fmaxf(lg[0], lg[1]), fmaxf(lg[2], lg[3]));
                float e0 = expf(lg[0] - mx), e1 = expf(lg[1] - mx);
                float e2 = expf(lg[2] - mx), e3 = expf(lg[3] - mx);
                float sI = e0 + e1 + e2 + e3;
                out[0] = e0 / sI; out[1] = e1 / sI; out[2] = e2 / sI; out[3] = e3 / sI;
            }
        }
    } else {
        // bu levels 1..5 (2048..128 nodes): all 64 bu blocks, per-level barrier
        for (int s = 1; s <= 5; s++) {
            int cnt = 1 << (12 - s);
            int lo = 4096 - (1 << (13 - s));
            int tiles = (cnt + 15) >> 4;
            for (int tile = gid; tile < tiles; tile += 64)
                gru_tile(false, lo, cnt, tile, gz, gr, gh, sU, sHp, sHr, slot, h4);
            gbar(&g_bar_bu[s - 1], 64, true);
        }
        // levels 6..12 (64..1 nodes): solo by bu block 0; others exit
        if (gid == 0) {
            for (int s = 6; s <= 12; s++) {
                int cnt = 1 << (12 - s);
                int lo = 4096 - (1 << (13 - s));
                int tiles = (cnt + 15) >> 4;
                for (int tile = 0; tile < tiles; tile++)
                    gru_tile(false, lo, cnt, tile, gz, gr, gh, sU, sHp, sHr, slot, h4);
            }
            gbar(&g_bar_td[8], 65, false);   // arrive at head barrier (release bu root)
        }
    }
}

// ---------------- launch ----------------
extern "C" void kernel_launch(void* const* d_in, const int* in_sizes, int n_in,
                              void* d_out, int out_size) {
    const float* td_x_word = (const float*)d_in[0];
    const float* bu_x_word = (const float*)d_in[1];
    const float* E_td  = (const float*)d_in[2];
    const float* Wz_td = (const float*)d_in[3];
    const float* Uz_td = (const float*)d_in[4];
    const float* bz_td = (const float*)d_in[5];
    const float* Wr_td = (const float*)d_in[6];
    const float* Ur_td = (const float*)d_in[7];
    const float* br_td = (const float*)d_in[8];
    const float* Wh_td = (const float*)d_in[9];
    const float* Uh_td = (const float*)d_in[10];
    const float* bh_td = (const float*)d_in[11];
    const float* E_bu  = (const float*)d_in[12];
    const float* Wz_bu = (const float*)d_in[13];
    const float* Uz_bu = (const float*)d_in[14];
    const float* bz_bu = (const float*)d_in[15];
    const float* Wr_bu = (const float*)d_in[16];
    const float* Ur_bu = (const float*)d_in[17];
    const float* br_bu = (const float*)d_in[18];
    const float* Wh_bu = (const float*)d_in[19];
    const float* Uh_bu = (const float*)d_in[20];
    const float* bh_bu = (const float*)d_in[21];
    const float* W1 = (const float*)d_in[22];
    const float* b1 = (const float*)d_in[23];
    const float* W4 = (const float*)d_in[24];
    const float* b4 = (const float*)d_in[25];

    const int* idx_td = (const int*)d_in[26];
    const int* idx_bu = (const int*)d_in[27];
    for (int i = 26; i < n_in; i++) {
        if (in_sizes[i] == NTD * 64) idx_td = (const int*)d_in[i];
        else if (in_sizes[i] == NBU * 64) idx_bu = (const int*)d_in[i];
    }

    const int smemE = (3 * 64 * WSTR + 192 + 2048 + 2048 + 2048) * 4;
    const int smemT = (3 * 64 * WSTR + 1024 + 1024) * 4;
    cudaFuncSetAttribute(k_embed, cudaFuncAttributeMaxDynamicSharedMemorySize, smemE);
    cudaFuncSetAttribute(k_tree, cudaFuncAttributeMaxDynamicSharedMemorySize, smemT);

    k_transpose<<<dim3((VOCAB + 63) / 64, 2), 256>>>(E_td, E_bu);

    const int NBLK = 148;
    k_embed<<<2 * NBLK, 256, smemE>>>(td_x_word, idx_td, bu_x_word, idx_bu,
                                      Wz_td, Wr_td, Wh_td, bz_td, br_td, bh_td,
                                      Wz_bu, Wr_bu, Wh_bu, bz_bu, br_bu, bh_bu, NBLK);

    k_tree<<<PBLK, 256, smemT>>>(Uz_td, Ur_td, Uh_td, Uz_bu, Ur_bu, Uh_bu,
                                 W1, b1, W4, b4, (float*)d_out);
}

// round 8
// speedup vs baseline: 1.5339x; 1.1833x over previous
#include <cuda_runtime.h>
#include <math.h>

#define HDIM 64
#define VOCAB 50000
#define NTD 8192
#define NBU 8191
#define LBU 4096
#define WSTR 68     // padded stride for weight matrices in shared
#define GRID 296    // 2 blocks per SM, all co-resident (148 or 152 SMs)
#define NTT 1564    // transpose tiles: 782 per table

// ---------------- device scratch (static allocations only) ----------------
__device__ float g_ET_td[(size_t)VOCAB * HDIM];   // E transposed: (V, H)
__device__ float g_ET_bu[(size_t)VOCAB * HDIM];
__device__ float g_zx_td[NTD * HDIM];
__device__ float g_rx_td[NTD * HDIM];
__device__ float g_hx_td[NTD * HDIM];
__device__ float g_zx_bu[NBU * HDIM];
__device__ float g_rx_bu[NBU * HDIM];
__device__ float g_hx_bu[NBU * HDIM];
__device__ float g_h_td[(NTD + 1) * HDIM];
__device__ float g_h_bu[NBU * HDIM];
__device__ float g_tdmax[64 * HDIM];
// g_ctr: [0]=transpose bar, [1]=embed bar, [2]=td join, [3..11]=td levels 5..13,
//        [12]=head (65), [13..19]=bu levels 1..7, [20]=final (GRID), [22],[23]=work queues
__device__ int g_ctr[32];   // zero-initialized at load; self-reset at kernel end

// ---------------- fast activations (ex2/rcp approx; abs err ~1e-6) ----------------
__device__ __forceinline__ float fex2(float x) { float r; asm("ex2.approx.f32 %0,%1;" : "=f"(r) : "f"(x)); return r; }
__device__ __forceinline__ float frcp(float x) { float r; asm("rcp.approx.f32 %0,%1;" : "=f"(r) : "f"(x)); return r; }
__device__ __forceinline__ float sigmf(float x) { return frcp(1.0f + fex2(-1.4426950408889634f * x)); }
__device__ __forceinline__ float tanhf_fast(float x) { return 2.0f * sigmf(2.0f * x) - 1.0f; }

// global barrier on g_ctr[idx]: arrive (release); optionally spin to target (acquire)
__device__ __forceinline__ void gbar(int idx, int target, bool wait) {
    __syncthreads();
    if (threadIdx.x == 0) {
        unsigned long long g;
        asm volatile("cvta.to.global.u64 %0, %1;" : "=l"(g) : "l"(&g_ctr[idx]));
        asm volatile("red.release.gpu.global.add.u32 [%0], 1;" :: "l"(g) : "memory");
        if (wait) {
            int v;
            do {
                asm volatile("ld.acquire.gpu.global.u32 %0, [%1];" : "=r"(v) : "l"(g) : "memory");
            } while (v < target);
        }
    }
    __syncthreads();
}

// ---------------- GRU for one 16-node tile (all 256 threads participate) ----------------
__device__ __forceinline__ void gru_tile(
    bool is_td, int lo, int cnt, int tile,
    const float* __restrict__ gz, const float* __restrict__ gr, const float* __restrict__ gh,
    const float* sU, float* sHp, float* sHr, int slot, int h4,
    bool useP, float4 paz, float4 par, float4 pah)
{
    int r = tile * 16 + slot;
    bool act = (r < cnt);
    float4 hp = make_float4(0.f, 0.f, 0.f, 0.f);
    float4 az, ar, ah;
    int outRow = 0;
    if (act) {
        int gi;
        if (is_td) {
            int o = lo + r;
            gi = o - 1;
            hp = *(const float4*)&g_h_td[((o - 1) >> 1) * 64 + h4];
            outRow = o;
        } else {
            int j = lo + r;
            gi = LBU + j;
            float4 a = *(const float4*)&g_h_bu[(2 * j) * 64 + h4];
            float4 b = *(const float4*)&g_h_bu[(2 * j + 1) * 64 + h4];
            hp = make_float4(a.x + b.x, a.y + b.y, a.z + b.z, a.w + b.w);
            outRow = gi;
        }
        if (useP) { az = paz; ar = par; ah = pah; }
        else {
            az = *(const float4*)&gz[gi * 64 + h4];
            ar = *(const float4*)&gr[gi * 64 + h4];
            ah = *(const float4*)&gh[gi * 64 + h4];
        }
    }
    *(float4*)&sHp[slot * 64 + h4] = hp;
    __syncthreads();
    float4 z = make_float4(0, 0, 0, 0), rr = make_float4(0, 0, 0, 0);
    if (act) {
        float4 mz = az, mr = ar;
        const float* hpv = &sHp[slot * 64];
#pragma unroll 4
        for (int k = 0; k < 64; k++) {
            float x = hpv[k];
            float4 uz4 = *(const float4*)&sU[0 * 64 * WSTR + k * WSTR + h4];
            float4 ur4 = *(const float4*)&sU[1 * 64 * WSTR + k * WSTR + h4];
            mz.x += uz4.x * x; mz.y += uz4.y * x; mz.z += uz4.z * x; mz.w += uz4.w * x;
            mr.x += ur4.x * x; mr.y += ur4.y * x; mr.z += ur4.z * x; mr.w += ur4.w * x;
        }
        z = make_float4(sigmf(mz.x), sigmf(mz.y), sigmf(mz.z), sigmf(mz.w));
        rr = make_float4(sigmf(mr.x), sigmf(mr.y), sigmf(mr.z), sigmf(mr.w));
    }
    float4 hr = make_float4(hp.x * rr.x, hp.y * rr.y, hp.z * rr.z, hp.w * rr.w);
    *(float4*)&sHr[slot * 64 + h4] = act ? hr : make_float4(0, 0, 0, 0);
    __syncthreads();
    if (act) {
        float4 mh = ah;
        const float* hrv = &sHr[slot * 64];
#pragma unroll 4
        for (int k = 0; k < 64; k++) {
            float x = hrv[k];
            float4 uh4 = *(const float4*)&sU[2 * 64 * WSTR + k * WSTR + h4];
            mh.x += uh4.x * x; mh.y += uh4.y * x; mh.z += uh4.z * x; mh.w += uh4.w * x;
        }
        float4 c = make_float4(tanhf_fast(mh.x), tanhf_fast(mh.y), tanhf_fast(mh.z), tanhf_fast(mh.w));
        float4 hn;
        hn.x = z.x * hp.x + (1.f - z.x) * c.x;
        hn.y = z.y * hp.y + (1.f - z.y) * c.y;
        hn.z = z.z * hp.z + (1.f - z.z) * c.z;
        hn.w = z.w * hp.w + (1.f - z.w) * c.w;
        if (is_td) *(float4*)&g_h_td[outRow * 64 + h4] = hn;
        else       *(float4*)&g_h_bu[outRow * 64 + h4] = hn;
    }
    __syncthreads();
}

// ---------------- THE kernel: transpose -> embed -> tree -> head ----------------
__global__ void __launch_bounds__(256, 2) k_mega(
    const float* __restrict__ E_td, const float* __restrict__ E_bu,
    const float* __restrict__ td_word, const int* __restrict__ td_idx,
    const float* __restrict__ bu_word, const int* __restrict__ bu_idx,
    const float* __restrict__ Wz_td, const float* __restrict__ Wr_td, const float* __restrict__ Wh_td,
    const float* __restrict__ bz_td, const float* __restrict__ br_td, const float* __restrict__ bh_td,
    const float* __restrict__ Wz_bu, const float* __restrict__ Wr_bu, const float* __restrict__ Wh_bu,
    const float* __restrict__ bz_bu, const float* __restrict__ br_bu, const float* __restrict__ bh_bu,
    const float* __restrict__ Uz_td, const float* __restrict__ Ur_td, const float* __restrict__ Uh_td,
    const float* __restrict__ Uz_bu, const float* __restrict__ Ur_bu, const float* __restrict__ Uh_bu,
    const float* __restrict__ W1, const float* __restrict__ b1,
    const float* __restrict__ W4, const float* __restrict__ b4,
    float* __restrict__ out)
{
    extern __shared__ float sm[];
    int bid = blockIdx.x;
    int tid = threadIdx.x;

    // ============ phase 1: transpose E (H,V) -> ET (V,H) ============
    {
        float (*tile)[65] = (float (*)[65])sm;
        if (bid == 0 && tid < 64) g_h_td[tid] = 0.f;     // node_h[0] = 0
        for (int ti = bid; ti < NTT; ti += GRID) {
            const float* E = (ti < 782) ? E_td : E_bu;
            float* ET = (ti < 782) ? g_ET_td : g_ET_bu;
            int v0 = ((ti < 782) ? ti : ti - 782) * 64;
            int rem = VOCAB - v0;                         // 64 normally, 16 for last tile
            __syncthreads();
#pragma unroll
            for (int it = 0; it < 4; it++) {
                int e = it * 256 + tid;
                int h = e >> 4, c = (e & 15) * 4;
                if (c < rem) {
                    float4 v = *(const float4*)&E[(size_t)h * VOCAB + v0 + c];
                    tile[h][c] = v.x; tile[h][c + 1] = v.y;
                    tile[h][c + 2] = v.z; tile[h][c + 3] = v.w;
                }
            }
            __syncthreads();
#pragma unroll
            for (int it = 0; it < 4; it++) {
                int e = it * 256 + tid;
                int v = e >> 4, c = (e & 15) * 4;
                if (v < rem)
                    *(float4*)&g_ET_td[0] , (void)0;   // placeholder removed below
            }
            // (real store loop)
#pragma unroll
            for (int it = 0; it < 4; it++) {
                int e = it * 256 + tid;
                int v = e >> 4, c = (e & 15) * 4;
                if (v < rem) {
                    float4 val = make_float4(tile[c][v], tile[c + 1][v], tile[c + 2][v], tile[c + 3][v]);
                    *(float4*)&ET[(size_t)(v0 + v) * 64 + c] = val;
                }
            }
        }
    }
    gbar(0, GRID, true);

    // ============ phase 2: embedding gather + gate pre-activations ============
    {
        float* sW = sm;                       // 3 * 64 * WSTR
        float* sb = sW + 3 * 64 * WSTR;       // 192
        float* sWord = sb + 192;              // 32 * 64
        float* sXe = sWord + 2048;            // 32 * 64
        int* sIdx = (int*)(sXe + 2048);       // 32 * 64
        __shared__ int sChunk;

        bool is_td = (bid < 148);
        const float* word = is_td ? td_word : bu_word;
        const int* idx = is_td ? td_idx : bu_idx;
        const float* ET = is_td ? g_ET_td : g_ET_bu;
        const float* Wz = is_td ? Wz_td : Wz_bu;
        const float* Wr = is_td ? Wr_td : Wr_bu;
        const float* Wh = is_td ? Wh_td : Wh_bu;
        const float* bz = is_td ? bz_td : bz_bu;
        const float* br = is_td ? br_td : br_bu;
        const float* bh = is_td ? bh_td : bh_bu;
        float* zx = is_td ? g_zx_td : g_zx_bu;
        float* rx = is_td ? g_rx_td : g_rx_bu;
        float* hx = is_td ? g_hx_td : g_hx_bu;
        int nNodes = is_td ? NTD : NBU;
        int qIdx = is_td ? 22 : 23;

        for (int g = 0; g < 3; g++) {
            const float* Wg = (g == 0) ? Wz : (g == 1) ? Wr : Wh;
            for (int e = tid; e < 4096; e += 256) {
                int hh = e >> 6, kk = e & 63;
                sW[g * 64 * WSTR + kk * WSTR + hh] = Wg[e];
            }
        }
        if (tid < 64) sb[tid] = bz[tid];
        else if (tid < 128) sb[tid] = br[tid - 64];
        else if (tid < 192) sb[tid] = bh[tid - 128];
        __syncthreads();

        int slot = tid >> 4;
        int t = tid & 15;
        int h4 = t * 4;

        for (;;) {
            if (tid == 0) sChunk = atomicAdd(&g_ctr[qIdx], 1);
            __syncthreads();
            int c = sChunk;
            if (c >= 256) break;
            int base = c * 32;
            int n0 = base + slot;
            int n1 = base + slot + 16;
            bool full = (base + 32 <= nNodes);
            bool a0 = full || (n0 < nNodes);
            bool a1 = full || (n1 < nNodes);
            if (a0) {
                *(int4*)&sIdx[slot * 64 + h4] = *(const int4*)&idx[n0 * 64 + h4];
                *(float4*)&sWord[slot * 64 + h4] = *(const float4*)&word[n0 * 64 + h4];
            }
            if (a1) {
                *(int4*)&sIdx[(slot + 16) * 64 + h4] = *(const int4*)&idx[n1 * 64 + h4];
                *(float4*)&sWord[(slot + 16) * 64 + h4] = *(const float4*)&word[n1 * 64 + h4];
            }
            __syncthreads();
            float4 acc0 = make_float4(0.f, 0.f, 0.f, 0.f);
            float4 acc1 = make_float4(0.f, 0.f, 0.f, 0.f);
            {
                const int* ip0 = &sIdx[slot * 64];
                const float* wp0 = &sWord[slot * 64];
                const int* ip1 = &sIdx[(slot + 16) * 64];
                const float* wp1 = &sWord[(slot + 16) * 64];
                if (full) {
#pragma unroll 4
                    for (int w = 0; w < 64; w++) {
                        float4 ea = *(const float4*)&ET[ip0[w] * 64 + h4];
                        float4 eb = *(const float4*)&ET[ip1[w] * 64 + h4];
                        float wa = wp0[w], wb = wp1[w];
                        acc0.x += ea.x * wa; acc0.y += ea.y * wa; acc0.z += ea.z * wa; acc0.w += ea.w * wa;
                        acc1.x += eb.x * wb; acc1.y += eb.y * wb; acc1.z += eb.z * wb; acc1.w += eb.w * wb;
                    }
                } else {
#pragma unroll 4
                    for (int w = 0; w < 64; w++) {
                        if (a0) {
                            float4 ea = *(const float4*)&ET[ip0[w] * 64 + h4];
                            float wa = wp0[w];
                            acc0.x += ea.x * wa; acc0.y += ea.y * wa; acc0.z += ea.z * wa; acc0.w += ea.w * wa;
                        }
                        if (a1) {
                            float4 eb = *(const float4*)&ET[ip1[w] * 64 + h4];
                            float wb = wp1[w];
                            acc1.x += eb.x * wb; acc1.y += eb.y * wb; acc1.z += eb.z * wb; acc1.w += eb.w * wb;
                        }
                    }
                }
            }
            *(float4*)&sXe[slot * 64 + h4] = acc0;
            *(float4*)&sXe[(slot + 16) * 64 + h4] = acc1;
            __syncthreads();
            {
                const float* xe0 = &sXe[slot * 64];
                const float* xe1 = &sXe[(slot + 16) * 64];
                float4 bzv = *(const float4*)&sb[0 * 64 + h4];
                float4 brv = *(const float4*)&sb[1 * 64 + h4];
                float4 bhv = *(const float4*)&sb[2 * 64 + h4];
                float4 az0 = bzv, ar0 = brv, ah0 = bhv;
                float4 az1 = bzv, ar1 = brv, ah1 = bhv;
#pragma unroll 4
                for (int k = 0; k < 64; k++) {
                    float4 wz4 = *(const float4*)&sW[0 * 64 * WSTR + k * WSTR + h4];
                    float4 wr4 = *(const float4*)&sW[1 * 64 * WSTR + k * WSTR + h4];
                    float4 wh4 = *(const float4*)&sW[2 * 64 * WSTR + k * WSTR + h4];
                    float x0 = xe0[k], x1 = xe1[k];
                    az0.x += wz4.x * x0; az0.y += wz4.y * x0; az0.z += wz4.z * x0; az0.w += wz4.w * x0;
                    ar0.x += wr4.x * x0; ar0.y += wr4.y * x0; ar0.z += wr4.z * x0; ar0.w += wr4.w * x0;
                    ah0.x += wh4.x * x0; ah0.y += wh4.y * x0; ah0.z += wh4.z * x0; ah0.w += wh4.w * x0;
                    az1.x += wz4.x * x1; az1.y += wz4.y * x1; az1.z += wz4.z * x1; az1.w += wz4.w * x1;
                    ar1.x += wr4.x * x1; ar1.y += wr4.y * x1; ar1.z += wr4.z * x1; ar1.w += wr4.w * x1;
                    ah1.x += wh4.x * x1; ah1.y += wh4.y * x1; ah1.z += wh4.z * x1; ah1.w += wh4.w * x1;
                }
#pragma unroll
                for (int p = 0; p < 2; p++) {
                    int n = p ? n1 : n0;
                    bool act = p ? a1 : a0;
                    float4 az = p ? az1 : az0, ar = p ? ar1 : ar0, ah = p ? ah1 : ah0;
                    if (!act) continue;
                    if (is_td || n >= LBU) {
                        *(float4*)&zx[n * 64 + h4] = az;
                        *(float4*)&rx[n * 64 + h4] = ar;
                        *(float4*)&hx[n * 64 + h4] = ah;
                    } else {
                        float4 lh;
                        lh.x = (1.f - sigmf(az.x)) * tanhf_fast(ah.x);
                        lh.y = (1.f - sigmf(az.y)) * tanhf_fast(ah.y);
                        lh.z = (1.f - sigmf(az.z)) * tanhf_fast(ah.z);
                        lh.w = (1.f - sigmf(az.w)) * tanhf_fast(ah.w);
                        *(float4*)&g_h_bu[n * 64 + h4] = lh;
                    }
                }
            }
            __syncthreads();
        }
    }
    gbar(1, GRID, bid < 128);

    // ============ phase 3: tree recurrences + head ============
    if (bid < 128) {
        float* sU = sm;                       // 3 * 64 * WSTR
        float* sHp = sU + 3 * 64 * WSTR;      // 16 * 64
        float* sHr = sHp + 1024;              // 16 * 64

        bool is_td = (bid < 64);
        int gid = is_td ? bid : bid - 64;

        const float* Uz = is_td ? Uz_td : Uz_bu;
        const float* Ur = is_td ? Ur_td : Ur_bu;
        const float* Uh = is_td ? Uh_td : Uh_bu;
        const float* gz = is_td ? g_zx_td : g_zx_bu;
        const float* gr = is_td ? g_rx_td : g_rx_bu;
        const float* gh = is_td ? g_hx_td : g_hx_bu;

        for (int g = 0; g < 3; g++) {
            const float* Ug = (g == 0) ? Uz : (g == 1) ? Ur : Uh;
            for (int e = tid; e < 4096; e += 256) {
                int hh = e >> 6, kk = e & 63;
                sU[g * 64 * WSTR + kk * WSTR + hh] = Ug[e];
            }
        }
        if (bid == 0) {
            // prefetch head weights into L2 (used ~tree-latency later)
            asm volatile("prefetch.global.L2 [%0];" :: "l"(&W1[tid * 32]));
            if (tid < 8) asm volatile("prefetch.global.L2 [%0];" :: "l"(&W4[tid * 32]));
        }
        __syncthreads();

        int slot = tid >> 4;
        int t = tid & 15;
        int h4 = t * 4;
        const float4 f40 = make_float4(0.f, 0.f, 0.f, 0.f);

        if (is_td) {
            // levels 1..4 (2..16 nodes, 1 tile each): solo by block 0
            if (gid == 0) {
                for (int s = 1; s <= 4; s++) {
                    int lo = (1 << s) - 1, cnt = 1 << s;
                    gru_tile(true, lo, cnt, 0, gz, gr, gh, sU, sHp, sHr, slot, h4, false, f40, f40, f40);
                }
            }
            // prefetch level-5 gates (cnt=32, lo=31)
            float4 paz = f40, par = f40, pah = f40;
            bool useP = false;
            {
                int r = gid * 16 + slot;
                if (r < 32) {
                    int gi = 30 + r;
                    paz = *(const float4*)&gz[gi * 64 + h4];
                    par = *(const float4*)&gr[gi * 64 + h4];
                    pah = *(const float4*)&gh[gi * 64 + h4];
                    useP = true;
                }
            }
            gbar(2, 64, true);
            // levels 5..13: 64 blocks, per-level barrier, gate prefetch across barrier
            for (int s = 5; s <= 13; s++) {
                int lo = (1 << s) - 1;
                int cnt = (s < 13) ? (1 << s) : 2;
                int tiles = (cnt + 15) >> 4;
                for (int tile = gid; tile < tiles; tile += 64)
                    gru_tile(true, lo, cnt, tile, gz, gr, gh, sU, sHp, sHr, slot, h4,
                             (tile == gid) && useP, paz, par, pah);
                useP = false;
                if (s < 13) {
                    int s2 = s + 1;
                    int lo2 = (1 << s2) - 1;
                    int cnt2 = (s2 < 13) ? (1 << s2) : 2;
                    int r = gid * 16 + slot;
                    if (r < cnt2) {
                        int gi = lo2 + r - 1;
                        paz = *(const float4*)&gz[gi * 64 + h4];
                        par = *(const float4*)&gr[gi * 64 + h4];
                        pah = *(const float4*)&gh[gi * 64 + h4];
                        useP = true;
                    }
                }
                gbar(3 + s - 5, 64, true);
            }
            // partial max over leaf rows 4096..8192
            if (tid < 64) {
                int h = tid;
                float m = -1e30f;
                for (int r = 4096 + gid; r <= NTD; r += 64)
                    m = fmaxf(m, g_h_td[r * 64 + h]);
                g_tdmax[gid * 64 + h] = m;
            }
            // head barrier: 64 td + bu block 0 = 65; only td block 0 waits
            gbar(12, 65, gid == 0);

            if (gid == 0) {
                __shared__ float fs[128], f1[64], lg[4];
                if (tid < 64) {
                    float m = -1e30f;
#pragma unroll 8
                    for (int b = 0; b < 64; b++) m = fmaxf(m, g_tdmax[b * 64 + tid]);
                    fs[tid] = m;
                } else if (tid < 128) {
                    fs[tid] = g_h_bu[(NBU - 1) * 64 + (tid - 64)];
                }
                __syncthreads();
                {
                    int row = tid >> 2, part = tid & 3;
                    float s = 0.f;
#pragma unroll
                    for (int i = 0; i < 8; i++) {
                        int k = part * 32 + i * 4;
                        float4 w = *(const float4*)&W1[row * 128 + k];
                        s += w.x * fs[k] + w.y * fs[k + 1] + w.z * fs[k + 2] + w.w * fs[k + 3];
                    }
                    s += __shfl_down_sync(0xffffffffu, s, 1);
                    s += __shfl_down_sync(0xffffffffu, s, 2);
                    if (part == 0) f1[row] = fmaxf(s + b1[row], 0.f);
                }
                __syncthreads();
                if (tid < 128) {
                    int row = tid >> 5, lane = tid & 31;
                    float s = W4[row * 64 + lane] * f1[lane] + W4[row * 64 + 32 + lane] * f1[32 + lane];
#pragma unroll
                    for (int o = 16; o > 0; o >>= 1) s += __shfl_down_sync(0xffffffffu, s, o);
                    if (lane == 0) lg[row] = s + b4[row];
                }
                __syncthreads();
                if (tid == 0) {
                    float mx = fmaxf(fmaxf(lg[0], lg[1]), fmaxf(lg[2], lg[3]));
                    float e0 = expf(lg[0] - mx), e1 = expf(lg[1] - mx);
                    float e2 = expf(lg[2] - mx), e3 = expf(lg[3] - mx);
                    float sI = e0 + e1 + e2 + e3;
                    out[0] = e0 / sI; out[1] = e1 / sI; out[2] = e2 / sI; out[3] = e3 / sI;
                }
            }
        } else {
            // bu levels 1..7 (2048..32 nodes): 64 blocks, per-level barrier + prefetch
            float4 paz = f40, par = f40, pah = f40;
            bool useP = false;
            {
                int r = gid * 16 + slot;          // level 1: lo=0, cnt=2048
                if (r < 2048) {
                    int gi = LBU + r;
                    paz = *(const float4*)&gz[gi * 64 + h4];
                    par = *(const float4*)&gr[gi * 64 + h4];
                    pah = *(const float4*)&gh[gi * 64 + h4];
                    useP = true;
                }
            }
            for (int s = 1; s <= 7; s++) {
                int cnt = 1 << (12 - s);
                int lo = 4096 - (1 << (13 - s));
                int tiles = cnt >> 4;
                for (int tile = gid; tile < tiles; tile += 64)
                    gru_tile(false, lo, cnt, tile, gz, gr, gh, sU, sHp, sHr, slot, h4,
                             (tile == gid) && useP, paz, par, pah);
                useP = false;
                {
                    int s2 = s + 1;
                    int cnt2 = 1 << (12 - s2);
                    int lo2 = 4096 - (1 << (13 - s2));
                    int r = gid * 16 + slot;
                    if (r < cnt2) {
                        int gi = LBU + lo2 + r;
                        paz = *(const float4*)&gz[gi * 64 + h4];
                        par = *(const float4*)&gr[gi * 64 + h4];
                        pah = *(const float4*)&gh[gi * 64 + h4];
                        useP = true;
                    }
                }
                gbar(13 + s - 1, 64, true);
            }
            // levels 8..12 (16..1 nodes): solo by bu block 0
            if (gid == 0) {
                for (int s = 8; s <= 12; s++) {
                    int cnt = 1 << (12 - s);
                    int lo = 4096 - (1 << (13 - s));
                    gru_tile(false, lo, cnt, 0, gz, gr, gh, sU, sHp, sHr, slot, h4,
                             (s == 8) && useP, paz, par, pah);
                }
                gbar(12, 65, false);   // arrive at head barrier (publishes bu root)
            }
        }
    }

    // ============ final barrier + counter reset ============
    gbar(20, GRID, bid == 0);
    if (bid == 0 && tid < 32) g_ctr[tid] = 0;
}

// ---------------- launch ----------------
extern "C" void kernel_launch(void* const* d_in, const int* in_sizes, int n_in,
                              void* d_out, int out_size) {
    const float* td_x_word = (const float*)d_in[0];
    const float* bu_x_word = (const float*)d_in[1];
    const float* E_td  = (const float*)d_in[2];
    const float* Wz_td = (const float*)d_in[3];
    const float* Uz_td = (const float*)d_in[4];
    const float* bz_td = (const float*)d_in[5];
    const float* Wr_td = (const float*)d_in[6];
    const float* Ur_td = (const float*)d_in[7];
    const float* br_td = (const float*)d_in[8];
    const float* Wh_td = (const float*)d_in[9];
    const float* Uh_td = (const float*)d_in[10];
    const float* bh_td = (const float*)d_in[11];
    const float* E_bu  = (const float*)d_in[12];
    const float* Wz_bu = (const float*)d_in[13];
    const float* Uz_bu = (const float*)d_in[14];
    const float* bz_bu = (const float*)d_in[15];
    const float* Wr_bu = (const float*)d_in[16];
    const float* Ur_bu = (const float*)d_in[17];
    const float* br_bu = (const float*)d_in[18];
    const float* Wh_bu = (const float*)d_in[19];
    const float* Uh_bu = (const float*)d_in[20];
    const float* bh_bu = (const float*)d_in[21];
    const float* W1 = (const float*)d_in[22];
    const float* b1 = (const float*)d_in[23];
    const float* W4 = (const float*)d_in[24];
    const float* b4 = (const float*)d_in[25];

    const int* idx_td = (const int*)d_in[26];
    const int* idx_bu = (const int*)d_in[27];
    for (int i = 26; i < n_in; i++) {
        if (in_sizes[i] == NTD * 64) idx_td = (const int*)d_in[i];
        else if (in_sizes[i] == NBU * 64) idx_bu = (const int*)d_in[i];
    }

    const int smemM = (3 * 64 * WSTR + 192 + 2048 + 2048 + 2048) * 4;   // 77568 B
    cudaFuncSetAttribute(k_mega, cudaFuncAttributeMaxDynamicSharedMemorySize, smemM);

    k_mega<<<GRID, 256, smemM>>>(
        E_td, E_bu, td_x_word, idx_td, bu_x_word, idx_bu,
        Wz_td, Wr_td, Wh_td, bz_td, br_td, bh_td,
        Wz_bu, Wr_bu, Wh_bu, bz_bu, br_bu, bh_bu,
        Uz_td, Ur_td, Uh_td, Uz_bu, Ur_bu, Uh_bu,
        W1, b1, W4, b4, (float*)d_out);
}